// round 9
// baseline (speedup 1.0000x reference)
#include <cuda_runtime.h>
#include <cuda_bf16.h>
#include <cstdint>

#define Bb 32
#define Ll 1024
#define Hh 512
#define NEG_INF_V (-1e7f)

// Scratch
__device__ float g_S[(size_t)Bb * Ll * Ll];                  // 128 MB
__device__ float g_rowmax[Bb * Ll];
__device__ float g_rowsum[Bb * Ll];
__device__ float g_colmax[Bb * Ll];
__device__ float g_colsum[Bb * Ll];
// bf16 hi/lo operand caches
__device__ __nv_bfloat16 g_qh[16777216], g_ql[16777216];     // q [b][l][h]
__device__ __nv_bfloat16 g_ah[16777216], g_al[16777216];     // a [b][l][h]
__device__ __nv_bfloat16 g_Pqh[33554432], g_Pql[33554432];   // exp(S-rowmax) [b][q][a]
__device__ __nv_bfloat16 g_Pah[33554432], g_Pal[33554432];   // exp(S-colmax) [b][q][a]

// ---------------------------------------------------------------------------
__device__ __forceinline__ uint32_t s2u(const void* p) {
    uint32_t a;
    asm("{ .reg .u64 t; cvta.to.shared.u64 t, %1; cvt.u32.u64 %0, t; }" : "=r"(a) : "l"(p));
    return a;
}
#define LDSM_X4(r0, r1, r2, r3, addr)                                        \
    asm volatile("ldmatrix.sync.aligned.m8n8.x4.shared.b16 {%0,%1,%2,%3}, [%4];" \
                 : "=r"(r0), "=r"(r1), "=r"(r2), "=r"(r3) : "r"(addr))
#define MMA_BF16(c, a, b)                                                    \
    asm volatile("mma.sync.aligned.m16n8k16.row.col.f32.bf16.bf16.f32 "      \
                 "{%0,%1,%2,%3}, {%4,%5,%6,%7}, {%8,%9}, {%0,%1,%2,%3};"     \
                 : "+f"((c)[0]), "+f"((c)[1]), "+f"((c)[2]), "+f"((c)[3])    \
                 : "r"((a)[0]), "r"((a)[1]), "r"((a)[2]), "r"((a)[3]),       \
                   "r"((b)[0]), "r"((b)[1]))

__device__ __forceinline__ void split2(float x0, float x1, uint32_t& h, uint32_t& l) {
    __nv_bfloat162 hb = __floats2bfloat162_rn(x0, x1);
    float r0 = x0 - __low2float(hb);
    float r1 = x1 - __high2float(hb);
    __nv_bfloat162 lb = __floats2bfloat162_rn(r0, r1);
    h = reinterpret_cast<uint32_t&>(hb);
    l = reinterpret_cast<uint32_t&>(lb);
}

#define LDP 72
#define TILE_B 18432
#define BUF_B (4 * TILE_B)

// ===== bf16 tile loaders (512 threads) =====================================
// contiguous: tile[128 rows][64 k] from hi/lo arrays, row stride ld (halves)
__device__ __forceinline__ void ldg_c(uint2 vh[4], uint2 vl[4],
    const __nv_bfloat16* __restrict__ hi, const __nv_bfloat16* __restrict__ lo,
    int ld, int k0, int tid)
{
#pragma unroll
    for (int i = 0; i < 4; i++) {
        int idx = (i << 9) + tid;
        int row = idx >> 4, c4 = idx & 15;
        size_t o = (size_t)row * ld + k0 + (c4 << 2);
        vh[i] = *reinterpret_cast<const uint2*>(hi + o);
        vl[i] = *reinterpret_cast<const uint2*>(lo + o);
    }
}
__device__ __forceinline__ void st_c(const uint2 vh[4], const uint2 vl[4],
    char* dh, char* dl, int tid)
{
#pragma unroll
    for (int i = 0; i < 4; i++) {
        int idx = (i << 9) + tid;
        int row = idx >> 4, c4 = idx & 15;
        uint32_t off = (uint32_t)(row * LDP + (c4 << 2)) * 2;
        *reinterpret_cast<uint2*>(dh + off) = vh[i];
        *reinterpret_cast<uint2*>(dl + off) = vl[i];
    }
}
// transposed: tile[n=128][k=64] from src[k][n], row stride ld (halves)
__device__ __forceinline__ void ldg_t(uint32_t vh[4][2], uint32_t vl[4][2],
    const __nv_bfloat16* __restrict__ hi, const __nv_bfloat16* __restrict__ lo,
    int ld, int tid)
{
#pragma unroll
    for (int i = 0; i < 4; i++) {
        int idx = (i << 9) + tid;
        int n = idx & 127, k4 = idx >> 7;
        const ushort* h0 = (const ushort*)hi + (size_t)(k4 << 2) * ld + n;
        const ushort* l0 = (const ushort*)lo + (size_t)(k4 << 2) * ld + n;
        vh[i][0] = (uint32_t)h0[0] | ((uint32_t)h0[ld] << 16);
        vh[i][1] = (uint32_t)h0[2 * (size_t)ld] | ((uint32_t)h0[3 * (size_t)ld] << 16);
        vl[i][0] = (uint32_t)l0[0] | ((uint32_t)l0[ld] << 16);
        vl[i][1] = (uint32_t)l0[2 * (size_t)ld] | ((uint32_t)l0[3 * (size_t)ld] << 16);
    }
}
__device__ __forceinline__ void st_t(const uint32_t vh[4][2], const uint32_t vl[4][2],
    char* dh, char* dl, int tid)
{
#pragma unroll
    for (int i = 0; i < 4; i++) {
        int idx = (i << 9) + tid;
        int n = idx & 127, k4 = idx >> 7;
        uint32_t off = (uint32_t)(n * LDP + (k4 << 2)) * 2;
        *reinterpret_cast<uint2*>(dh + off) = make_uint2(vh[i][0], vh[i][1]);
        *reinterpret_cast<uint2*>(dl + off) = make_uint2(vl[i][0], vl[i][1]);
    }
}

// ---- per-warp body: one 64-wide K chunk, warp tile 32(M) x 32(N) ----------
__device__ __forceinline__ void mma_chunk32(float acc[2][4][4],
    uint32_t ah_b, uint32_t al_b, uint32_t bh_b, uint32_t bl_b,
    int wm, int wn, int lane)
{
    const int l16 = lane & 15, lk = lane >> 4;
    const int bn = ((lane >> 4) << 3) + (lane & 7);   // n row for B x4
    const int bk = ((lane >> 3) & 1) << 3;            // k half for B x4
#pragma unroll
    for (int ks = 0; ks < 4; ks++) {
        const int k0 = ks << 4;
        uint32_t bh[4][2], bl[4][2], af[2][4];
#pragma unroll
        for (int g = 0; g < 2; g++) {
            uint32_t boff = (uint32_t)((wn + g * 16 + bn) * LDP + k0 + bk) * 2;
            LDSM_X4(bh[2*g][0], bh[2*g][1], bh[2*g+1][0], bh[2*g+1][1], bh_b + boff);
            LDSM_X4(bl[2*g][0], bl[2*g][1], bl[2*g+1][0], bl[2*g+1][1], bl_b + boff);
        }
#pragma unroll
        for (int mt = 0; mt < 2; mt++) {
            uint32_t aoff = (uint32_t)((wm + mt * 16 + l16) * LDP + k0 + lk * 8) * 2;
            LDSM_X4(af[mt][0], af[mt][1], af[mt][2], af[mt][3], ah_b + aoff);
        }
#pragma unroll
        for (int mt = 0; mt < 2; mt++)
#pragma unroll
            for (int nt = 0; nt < 4; nt++) {
                MMA_BF16(acc[mt][nt], af[mt], bh[nt]);
                MMA_BF16(acc[mt][nt], af[mt], bl[nt]);
            }
#pragma unroll
        for (int mt = 0; mt < 2; mt++) {
            uint32_t aoff = (uint32_t)((wm + mt * 16 + l16) * LDP + k0 + lk * 8) * 2;
            LDSM_X4(af[mt][0], af[mt][1], af[mt][2], af[mt][3], al_b + aoff);
        }
#pragma unroll
        for (int mt = 0; mt < 2; mt++)
#pragma unroll
            for (int nt = 0; nt < 4; nt++)
                MMA_BF16(acc[mt][nt], af[mt], bh[nt]);
    }
}

// ===========================================================================
// Kernel 0: prep — q,a -> bf16 hi/lo caches
// ===========================================================================
__global__ void __launch_bounds__(256) prep_kernel(
    const float4* __restrict__ q4, const float4* __restrict__ a4)
{
    int idx = blockIdx.x * 256 + threadIdx.x;     // 0 .. 8388607
    int isA = idx >> 22;                          // >= 4194304 -> a
    int base = idx & 4194303;
    float4 v = (isA ? a4 : q4)[base];
    uint32_t h01, l01, h23, l23;
    split2(v.x, v.y, h01, l01);
    split2(v.z, v.w, h23, l23);
    uint2* dh = reinterpret_cast<uint2*>(isA ? g_ah : g_qh);
    uint2* dl = reinterpret_cast<uint2*>(isA ? g_al : g_ql);
    dh[base] = make_uint2(h01, h23);
    dl[base] = make_uint2(l01, l23);
}

// ===========================================================================
// Kernel 1: S = mask(temp * q a^T) — pipelined bf16x3, tile 128x128, K=512
// ===========================================================================
__global__ void __launch_bounds__(512, 1) score_tc(
    const int* __restrict__ qm, const int* __restrict__ am,
    const float* __restrict__ temp)
{
    extern __shared__ char sm[];
    __shared__ int s_qm[128], s_am[128];

    const int tid = threadIdx.x, lane = tid & 31, wid = tid >> 5;
    const int wm = (wid & 3) * 32, wn = (wid >> 2) * 32;
    const int b = blockIdx.z, m0 = blockIdx.y << 7, n0 = blockIdx.x << 7;

    if (tid < 128) { s_qm[tid] = qm[b * Ll + m0 + tid]; s_am[tid] = am[b * Ll + n0 + tid]; }

    const size_t qoff = ((size_t)b * Ll + m0) * Hh;
    const size_t aoff = ((size_t)b * Ll + n0) * Hh;

    uint2 vah[4], val_[4], vbh[4], vbl[4];
    ldg_c(vah, val_, g_qh + qoff, g_ql + qoff, Hh, 0, tid);
    ldg_c(vbh, vbl, g_ah + aoff, g_al + aoff, Hh, 0, tid);
    st_c(vah, val_, sm, sm + TILE_B, tid);
    st_c(vbh, vbl, sm + 2 * TILE_B, sm + 3 * TILE_B, tid);
    __syncthreads();

    float acc[2][4][4] = {};
    for (int kc = 0; kc < 8; kc++) {
        int nk = kc + 1;
        if (nk < 8) {
            ldg_c(vah, val_, g_qh + qoff, g_ql + qoff, Hh, nk << 6, tid);
            ldg_c(vbh, vbl, g_ah + aoff, g_al + aoff, Hh, nk << 6, tid);
        }
        char* cur = sm + (kc & 1) * BUF_B;
        mma_chunk32(acc, s2u(cur), s2u(cur + TILE_B), s2u(cur + 2 * TILE_B),
                    s2u(cur + 3 * TILE_B), wm, wn, lane);
        if (nk < 8) {
            char* nb = sm + (nk & 1) * BUF_B;
            st_c(vah, val_, nb, nb + TILE_B, tid);
            st_c(vbh, vbl, nb + 2 * TILE_B, nb + 3 * TILE_B, tid);
        }
        __syncthreads();
    }

    const float t = *temp;
#pragma unroll
    for (int mt = 0; mt < 2; mt++)
#pragma unroll
        for (int h2 = 0; h2 < 2; h2++) {
            int mloc = wm + mt * 16 + (lane >> 2) + h2 * 8;
            int qv = s_qm[mloc];
            float* row = g_S + ((size_t)b * Ll + m0 + mloc) * Ll + n0 + wn + (lane & 3) * 2;
#pragma unroll
            for (int nt = 0; nt < 4; nt++) {
                int c = wn + nt * 8 + (lane & 3) * 2;
                float2 v;
                v.x = (qv && s_am[c])     ? acc[mt][nt][h2 * 2]     * t : NEG_INF_V;
                v.y = (qv && s_am[c + 1]) ? acc[mt][nt][h2 * 2 + 1] * t : NEG_INF_V;
                *reinterpret_cast<float2*>(row + nt * 8) = v;
            }
        }
}

// ===========================================================================
// Kernel 2: per-row stats + write Pq = exp(S - rowmax) hi/lo
// ===========================================================================
__global__ void __launch_bounds__(128) rowstats_kernel()
{
    const int row = blockIdx.x;
    const float* Sr = g_S + (size_t)row * Ll;
    const int tid = threadIdx.x;

    float v[8];
    float m = -3.4e38f;
#pragma unroll
    for (int i = 0; i < 8; i++) { v[i] = Sr[i * 128 + tid]; m = fmaxf(m, v[i]); }
#pragma unroll
    for (int o = 16; o; o >>= 1) m = fmaxf(m, __shfl_xor_sync(0xffffffffu, m, o));
    __shared__ float smx[4];
    if ((tid & 31) == 0) smx[tid >> 5] = m;
    __syncthreads();
    m = fmaxf(fmaxf(smx[0], smx[1]), fmaxf(smx[2], smx[3]));

    ushort* ph = (ushort*)g_Pqh + (size_t)row * Ll;
    ushort* pl = (ushort*)g_Pql + (size_t)row * Ll;
    float s = 0.f;
#pragma unroll
    for (int i = 0; i < 8; i++) {
        float e = __expf(v[i] - m);
        s += e;
        __nv_bfloat16 hb = __float2bfloat16_rn(e);
        float r = e - __bfloat162float(hb);
        __nv_bfloat16 lb = __float2bfloat16_rn(r);
        ph[i * 128 + tid] = *reinterpret_cast<ushort*>(&hb);
        pl[i * 128 + tid] = *reinterpret_cast<ushort*>(&lb);
    }
#pragma unroll
    for (int o = 16; o; o >>= 1) s += __shfl_xor_sync(0xffffffffu, s, o);
    __shared__ float ssm[4];
    if ((tid & 31) == 0) ssm[tid >> 5] = s;
    __syncthreads();
    if (tid == 0) { g_rowmax[row] = m; g_rowsum[row] = ssm[0] + ssm[1] + ssm[2] + ssm[3]; }
}

// ===========================================================================
// Kernel 3: per-column stats + write Pa = exp(S - colmax) hi/lo
// grid (8, 32); block 256 = 32 colgroups x 8 rowslices
// ===========================================================================
__global__ void __launch_bounds__(256) colstats_kernel()
{
    const int b = blockIdx.y;
    const int cg = threadIdx.x & 31;
    const int rs = threadIdx.x >> 5;
    const int c0 = blockIdx.x * 128 + cg * 4;
    const float* base = g_S + (size_t)b * Ll * Ll;
    __shared__ float4 red[256];

    float4 mx = make_float4(-3.4e38f, -3.4e38f, -3.4e38f, -3.4e38f);
    for (int r = rs * 128; r < rs * 128 + 128; r++) {
        float4 v = *reinterpret_cast<const float4*>(base + (size_t)r * Ll + c0);
        mx.x = fmaxf(mx.x, v.x); mx.y = fmaxf(mx.y, v.y);
        mx.z = fmaxf(mx.z, v.z); mx.w = fmaxf(mx.w, v.w);
    }
    red[threadIdx.x] = mx;
    __syncthreads();
    if (rs == 0) {
#pragma unroll
        for (int k = 1; k < 8; k++) {
            float4 o = red[k * 32 + cg];
            mx.x = fmaxf(mx.x, o.x); mx.y = fmaxf(mx.y, o.y);
            mx.z = fmaxf(mx.z, o.z); mx.w = fmaxf(mx.w, o.w);
        }
        red[cg] = mx;
    }
    __syncthreads();
    mx = red[cg];
    __syncthreads();

    uint2* pah = reinterpret_cast<uint2*>((ushort*)g_Pah + (size_t)b * Ll * Ll);
    uint2* pal = reinterpret_cast<uint2*>((ushort*)g_Pal + (size_t)b * Ll * Ll);
    float4 s4 = make_float4(0.f, 0.f, 0.f, 0.f);
    for (int r = rs * 128; r < rs * 128 + 128; r++) {
        float4 v = *reinterpret_cast<const float4*>(base + (size_t)r * Ll + c0);
        float e0 = __expf(v.x - mx.x), e1 = __expf(v.y - mx.y);
        float e2 = __expf(v.z - mx.z), e3 = __expf(v.w - mx.w);
        s4.x += e0; s4.y += e1; s4.z += e2; s4.w += e3;
        uint32_t h01, l01, h23, l23;
        split2(e0, e1, h01, l01);
        split2(e2, e3, h23, l23);
        size_t po = ((size_t)r * Ll + c0) >> 2;
        pah[po] = make_uint2(h01, h23);
        pal[po] = make_uint2(l01, l23);
    }
    red[threadIdx.x] = s4;
    __syncthreads();
    if (rs == 0) {
#pragma unroll
        for (int k = 1; k < 8; k++) {
            float4 o = red[k * 32 + cg];
            s4.x += o.x; s4.y += o.y; s4.z += o.z; s4.w += o.w;
        }
        *reinterpret_cast<float4*>(g_colmax + b * Ll + c0) = mx;
        *reinterpret_cast<float4*>(g_colsum + b * Ll + c0) = s4;
    }
}

// ===========================================================================
// Kernel 4: q_s = Pq @ a / rowsum — M=q, N=h, K=a; epilogue copies q
// ===========================================================================
__global__ void __launch_bounds__(512, 1) gemmQ_tc(
    const float4* __restrict__ q4, float* __restrict__ out)
{
    extern __shared__ char sm[];
    const int tid = threadIdx.x, lane = tid & 31, wid = tid >> 5;
    const int wm = (wid & 3) * 32, wn = (wid >> 2) * 32;
    const int b = blockIdx.z, m0 = blockIdx.y << 7, n0 = blockIdx.x << 7;

    const size_t poff = ((size_t)b * Ll + m0) * Ll;
    const __nv_bfloat16* Ph = g_Pqh + poff;
    const __nv_bfloat16* Pl = g_Pql + poff;
    const size_t boff = (size_t)b * Ll * Hh + n0;

    uint2 vah[4], val_[4];
    uint32_t vbh[4][2], vbl[4][2];
    ldg_c(vah, val_, Ph, Pl, Ll, 0, tid);
    ldg_t(vbh, vbl, g_ah + boff, g_al + boff, Hh, tid);
    st_c(vah, val_, sm, sm + TILE_B, tid);
    st_t(vbh, vbl, sm + 2 * TILE_B, sm + 3 * TILE_B, tid);
    __syncthreads();

    float acc[2][4][4] = {};
    for (int kc = 0; kc < 16; kc++) {
        int nk = kc + 1;
        if (nk < 16) {
            ldg_c(vah, val_, Ph, Pl, Ll, nk << 6, tid);
            ldg_t(vbh, vbl, g_ah + boff + (size_t)(nk << 6) * Hh,
                  g_al + boff + (size_t)(nk << 6) * Hh, Hh, tid);
        }
        char* cur = sm + (kc & 1) * BUF_B;
        mma_chunk32(acc, s2u(cur), s2u(cur + TILE_B), s2u(cur + 2 * TILE_B),
                    s2u(cur + 3 * TILE_B), wm, wn, lane);
        if (nk < 16) {
            char* nb = sm + (nk & 1) * BUF_B;
            st_c(vah, val_, nb, nb + TILE_B, tid);
            st_t(vbh, vbl, nb + 2 * TILE_B, nb + 3 * TILE_B, tid);
        }
        __syncthreads();
    }

#pragma unroll
    for (int mt = 0; mt < 2; mt++)
#pragma unroll
        for (int h2 = 0; h2 < 2; h2++) {
            int mloc = wm + mt * 16 + (lane >> 2) + h2 * 8;
            int m = m0 + mloc;
            float inv = 1.f / g_rowsum[b * Ll + m];
            float* row = out + ((size_t)b * Ll + m) * 1024 + 512 + n0 + wn + (lane & 3) * 2;
#pragma unroll
            for (int nt = 0; nt < 4; nt++) {
                float2 v;
                v.x = acc[mt][nt][h2 * 2] * inv;
                v.y = acc[mt][nt][h2 * 2 + 1] * inv;
                *reinterpret_cast<float2*>(row + nt * 8) = v;
            }
        }

    // copy q block into lower half: rows m0..m0+128, cols n0..n0+128
    float4* out4 = reinterpret_cast<float4*>(out);
#pragma unroll
    for (int i = 0; i < 8; i++) {
        int idx = (i << 9) + tid;
        int row = idx >> 5, c = idx & 31;
        size_t orow = (size_t)b * Ll + m0 + row;
        out4[orow * 256 + (n0 >> 2) + c] = q4[orow * 128 + (n0 >> 2) + c];
    }
}

// ===========================================================================
// Kernel 5: a_s = Pa^T @ q / colsum — M=a, N=h, K=q; epilogue copies a
// ===========================================================================
__global__ void __launch_bounds__(512, 1) gemmA_tc(
    const float4* __restrict__ a4, float* __restrict__ out)
{
    extern __shared__ char sm[];
    const int tid = threadIdx.x, lane = tid & 31, wid = tid >> 5;
    const int wm = (wid & 3) * 32, wn = (wid >> 2) * 32;
    const int b = blockIdx.z, m0 = blockIdx.y << 7, n0 = blockIdx.x << 7;

    const size_t paoff = (size_t)b * Ll * Ll + m0;   // [q=k][a=m0+n]
    const size_t boff = (size_t)b * Ll * Hh + n0;

    uint32_t vah[4][2], val_[4][2], vbh[4][2], vbl[4][2];
    ldg_t(vah, val_, g_Pah + paoff, g_Pal + paoff, Ll, tid);
    ldg_t(vbh, vbl, g_qh + boff, g_ql + boff, Hh, tid);
    st_t(vah, val_, sm, sm + TILE_B, tid);
    st_t(vbh, vbl, sm + 2 * TILE_B, sm + 3 * TILE_B, tid);
    __syncthreads();

    float acc[2][4][4] = {};
    for (int kc = 0; kc < 16; kc++) {
        int nk = kc + 1;
        if (nk < 16) {
            ldg_t(vah, val_, g_Pah + paoff + (size_t)(nk << 6) * Ll,
                  g_Pal + paoff + (size_t)(nk << 6) * Ll, Ll, tid);
            ldg_t(vbh, vbl, g_qh + boff + (size_t)(nk << 6) * Hh,
                  g_ql + boff + (size_t)(nk << 6) * Hh, Hh, tid);
        }
        char* cur = sm + (kc & 1) * BUF_B;
        mma_chunk32(acc, s2u(cur), s2u(cur + TILE_B), s2u(cur + 2 * TILE_B),
                    s2u(cur + 3 * TILE_B), wm, wn, lane);
        if (nk < 16) {
            char* nb = sm + (nk & 1) * BUF_B;
            st_t(vah, val_, nb, nb + TILE_B, tid);
            st_t(vbh, vbl, nb + 2 * TILE_B, nb + 3 * TILE_B, tid);
        }
        __syncthreads();
    }

    const size_t OUT2 = (size_t)Bb * Ll * 1024;
#pragma unroll
    for (int mt = 0; mt < 2; mt++)
#pragma unroll
        for (int h2 = 0; h2 < 2; h2++) {
            int mloc = wm + mt * 16 + (lane >> 2) + h2 * 8;
            int m = m0 + mloc;
            float inv = 1.f / g_colsum[b * Ll + m];
            float* row = out + OUT2 + ((size_t)b * Ll + m) * 1024 + 512 + n0 + wn + (lane & 3) * 2;
#pragma unroll
            for (int nt = 0; nt < 4; nt++) {
                float2 v;
                v.x = acc[mt][nt][h2 * 2] * inv;
                v.y = acc[mt][nt][h2 * 2 + 1] * inv;
                *reinterpret_cast<float2*>(row + nt * 8) = v;
            }
        }

    // copy a block into lower half of out2
    float4* out4 = reinterpret_cast<float4*>(out + OUT2);
#pragma unroll
    for (int i = 0; i < 8; i++) {
        int idx = (i << 9) + tid;
        int row = idx >> 5, c = idx & 31;
        size_t orow = (size_t)b * Ll + m0 + row;
        out4[orow * 256 + (n0 >> 2) + c] = a4[orow * 128 + (n0 >> 2) + c];
    }
}

// ===========================================================================
extern "C" void kernel_launch(void* const* d_in, const int* in_sizes, int n_in,
                              void* d_out, int out_size)
{
    const float* q    = (const float*)d_in[0];
    const float* a    = (const float*)d_in[1];
    const int*   qm   = (const int*)  d_in[2];
    const int*   am   = (const int*)  d_in[3];
    const float* temp = (const float*)d_in[4];
    float* out = (float*)d_out;

    const int DSMEM = 2 * BUF_B;   // 147456
    cudaFuncSetAttribute(score_tc, cudaFuncAttributeMaxDynamicSharedMemorySize, DSMEM);
    cudaFuncSetAttribute(gemmQ_tc, cudaFuncAttributeMaxDynamicSharedMemorySize, DSMEM);
    cudaFuncSetAttribute(gemmA_tc, cudaFuncAttributeMaxDynamicSharedMemorySize, DSMEM);

    prep_kernel<<<32768, 256>>>((const float4*)q, (const float4*)a);
    score_tc<<<dim3(8, 8, 32), 512, DSMEM>>>(qm, am, temp);
    rowstats_kernel<<<Bb * Ll, 128>>>();
    colstats_kernel<<<dim3(8, 32), 256>>>();
    gemmQ_tc<<<dim3(4, 8, 32), 512, DSMEM>>>((const float4*)q, out);
    gemmA_tc<<<dim3(4, 8, 32), 512, DSMEM>>>((const float4*)a, out);
}

// round 10
// speedup vs baseline: 1.3841x; 1.3841x over previous
#include <cuda_runtime.h>
#include <cuda_bf16.h>
#include <cuda_fp16.h>
#include <cstdint>

#define Bb 32
#define Ll 1024
#define Hh 512
#define NEG_INF_V (-1e7f)

// Scratch
__device__ float g_S[(size_t)Bb * Ll * Ll];                  // 128 MB
__device__ float g_rowmax[Bb * Ll];
__device__ float g_rowsum[Bb * Ll];
__device__ float g_colmax[Bb * Ll];
__device__ float g_colsum[Bb * Ll];
// operand caches: bf16 hi/lo (score), fp16 (output gemms)
__device__ __nv_bfloat16 g_qh[16777216], g_ql[16777216];
__device__ __nv_bfloat16 g_ah[16777216], g_al[16777216];
__device__ __half        g_qe[16777216], g_ae[16777216];

// ---------------------------------------------------------------------------
__device__ __forceinline__ uint32_t s2u(const void* p) {
    uint32_t a;
    asm("{ .reg .u64 t; cvta.to.shared.u64 t, %1; cvt.u32.u64 %0, t; }" : "=r"(a) : "l"(p));
    return a;
}
#define LDSM_X4(r0, r1, r2, r3, addr)                                        \
    asm volatile("ldmatrix.sync.aligned.m8n8.x4.shared.b16 {%0,%1,%2,%3}, [%4];" \
                 : "=r"(r0), "=r"(r1), "=r"(r2), "=r"(r3) : "r"(addr))
#define MMA_BF16(c, a, b)                                                    \
    asm volatile("mma.sync.aligned.m16n8k16.row.col.f32.bf16.bf16.f32 "      \
                 "{%0,%1,%2,%3}, {%4,%5,%6,%7}, {%8,%9}, {%0,%1,%2,%3};"     \
                 : "+f"((c)[0]), "+f"((c)[1]), "+f"((c)[2]), "+f"((c)[3])    \
                 : "r"((a)[0]), "r"((a)[1]), "r"((a)[2]), "r"((a)[3]),       \
                   "r"((b)[0]), "r"((b)[1]))
#define MMA_FP16(c, a, b)                                                    \
    asm volatile("mma.sync.aligned.m16n8k16.row.col.f32.f16.f16.f32 "        \
                 "{%0,%1,%2,%3}, {%4,%5,%6,%7}, {%8,%9}, {%0,%1,%2,%3};"     \
                 : "+f"((c)[0]), "+f"((c)[1]), "+f"((c)[2]), "+f"((c)[3])    \
                 : "r"((a)[0]), "r"((a)[1]), "r"((a)[2]), "r"((a)[3]),       \
                   "r"((b)[0]), "r"((b)[1]))

__device__ __forceinline__ void split2(float x0, float x1, uint32_t& h, uint32_t& l) {
    __nv_bfloat162 hb = __floats2bfloat162_rn(x0, x1);
    float r0 = x0 - __low2float(hb);
    float r1 = x1 - __high2float(hb);
    __nv_bfloat162 lb = __floats2bfloat162_rn(r0, r1);
    h = reinterpret_cast<uint32_t&>(hb);
    l = reinterpret_cast<uint32_t&>(lb);
}
__device__ __forceinline__ uint32_t pack_h2(float x0, float x1) {
    __half2 h = __floats2half2_rn(x0, x1);
    return reinterpret_cast<uint32_t&>(h);
}

#define LDP 72
#define TILE_B 18432              // 128 rows x 72 halves x 2B
#define BUF4_B (4 * TILE_B)       // score: ah, al, bh, bl
#define BUF2_B (2 * TILE_B)       // gemm: a, b

// ===== score-side bf16 tile loaders (512 threads) ==========================
__device__ __forceinline__ void ldg_c(uint2 vh[4], uint2 vl[4],
    const __nv_bfloat16* __restrict__ hi, const __nv_bfloat16* __restrict__ lo,
    int ld, int k0, int tid)
{
#pragma unroll
    for (int i = 0; i < 4; i++) {
        int idx = (i << 9) + tid;
        int row = idx >> 4, c4 = idx & 15;
        size_t o = (size_t)row * ld + k0 + (c4 << 2);
        vh[i] = *reinterpret_cast<const uint2*>(hi + o);
        vl[i] = *reinterpret_cast<const uint2*>(lo + o);
    }
}
__device__ __forceinline__ void st_c(const uint2 vh[4], const uint2 vl[4],
    char* dh, char* dl, int tid)
{
#pragma unroll
    for (int i = 0; i < 4; i++) {
        int idx = (i << 9) + tid;
        int row = idx >> 4, c4 = idx & 15;
        uint32_t off = (uint32_t)(row * LDP + (c4 << 2)) * 2;
        *reinterpret_cast<uint2*>(dh + off) = vh[i];
        *reinterpret_cast<uint2*>(dl + off) = vl[i];
    }
}

// ===== gemm-side fp16 loaders ==============================================
// A (k-major, from fp32 S with fused exp): tile[128 rows][64 k]
__device__ __forceinline__ void ldg_S(float4 v[4],
    const float* __restrict__ src, int k0, int tid)
{
#pragma unroll
    for (int i = 0; i < 4; i++) {
        int idx = (i << 9) + tid;
        int row = idx >> 4, c4 = idx & 15;
        v[i] = *reinterpret_cast<const float4*>(src + (size_t)row * Ll + k0 + (c4 << 2));
    }
}
__device__ __forceinline__ void st_exp_h(const float4 v[4], char* d,
    const float* __restrict__ bias, int tid)
{
#pragma unroll
    for (int i = 0; i < 4; i++) {
        int idx = (i << 9) + tid;
        int row = idx >> 4, c4 = idx & 15;
        float bm = bias[row];
        uint32_t p0 = pack_h2(__expf(v[i].x - bm), __expf(v[i].y - bm));
        uint32_t p1 = pack_h2(__expf(v[i].z - bm), __expf(v[i].w - bm));
        uint32_t off = (uint32_t)(row * LDP + (c4 << 2)) * 2;
        *reinterpret_cast<uint2*>(d + off) = make_uint2(p0, p1);
    }
}
// A transposed from fp32 S with fused exp: tile[n=128][k=64] = S[k][m0+n]
__device__ __forceinline__ void ldg_St(float4 v[4],
    const float* __restrict__ src, int tid)   // src = S + k0*Ll + m0
{
#pragma unroll
    for (int i = 0; i < 4; i++) {
        int idx = (i << 9) + tid;
        int n = idx & 127, k4 = idx >> 7;
        const float* s0 = src + (size_t)(k4 << 2) * Ll + n;
        v[i].x = s0[0];
        v[i].y = s0[Ll];
        v[i].z = s0[2 * (size_t)Ll];
        v[i].w = s0[3 * (size_t)Ll];
    }
}
__device__ __forceinline__ void st_exp_h_t(const float4 v[4], char* d,
    const float* __restrict__ bias, int tid)
{
#pragma unroll
    for (int i = 0; i < 4; i++) {
        int idx = (i << 9) + tid;
        int n = idx & 127, k4 = idx >> 7;
        float bm = bias[n];
        uint32_t p0 = pack_h2(__expf(v[i].x - bm), __expf(v[i].y - bm));
        uint32_t p1 = pack_h2(__expf(v[i].z - bm), __expf(v[i].w - bm));
        uint32_t off = (uint32_t)(n * LDP + (k4 << 2)) * 2;
        *reinterpret_cast<uint2*>(d + off) = make_uint2(p0, p1);
    }
}
// B transposed from fp16 cache: tile[n=128][k=64] = src[k][n]
__device__ __forceinline__ void ldg_ht(uint32_t v[4][2],
    const __half* __restrict__ src, int ld, int tid)
{
#pragma unroll
    for (int i = 0; i < 4; i++) {
        int idx = (i << 9) + tid;
        int n = idx & 127, k4 = idx >> 7;
        const ushort* h0 = (const ushort*)src + (size_t)(k4 << 2) * ld + n;
        v[i][0] = (uint32_t)h0[0] | ((uint32_t)h0[ld] << 16);
        v[i][1] = (uint32_t)h0[2 * (size_t)ld] | ((uint32_t)h0[3 * (size_t)ld] << 16);
    }
}
__device__ __forceinline__ void st_ht(const uint32_t v[4][2], char* d, int tid)
{
#pragma unroll
    for (int i = 0; i < 4; i++) {
        int idx = (i << 9) + tid;
        int n = idx & 127, k4 = idx >> 7;
        uint32_t off = (uint32_t)(n * LDP + (k4 << 2)) * 2;
        *reinterpret_cast<uint2*>(d + off) = make_uint2(v[i][0], v[i][1]);
    }
}

// ---- bf16x3 chunk (score): warp tile 32x32, K=64 --------------------------
__device__ __forceinline__ void mma_chunk3(float acc[2][4][4],
    uint32_t ah_b, uint32_t al_b, uint32_t bh_b, uint32_t bl_b,
    int wm, int wn, int lane)
{
    const int l16 = lane & 15, lk = lane >> 4;
    const int bn = ((lane >> 4) << 3) + (lane & 7);
    const int bk = ((lane >> 3) & 1) << 3;
#pragma unroll
    for (int ks = 0; ks < 4; ks++) {
        const int k0 = ks << 4;
        uint32_t bh[4][2], bl[4][2], af[2][4];
#pragma unroll
        for (int g = 0; g < 2; g++) {
            uint32_t boff = (uint32_t)((wn + g * 16 + bn) * LDP + k0 + bk) * 2;
            LDSM_X4(bh[2*g][0], bh[2*g][1], bh[2*g+1][0], bh[2*g+1][1], bh_b + boff);
            LDSM_X4(bl[2*g][0], bl[2*g][1], bl[2*g+1][0], bl[2*g+1][1], bl_b + boff);
        }
#pragma unroll
        for (int mt = 0; mt < 2; mt++) {
            uint32_t aoff = (uint32_t)((wm + mt * 16 + l16) * LDP + k0 + lk * 8) * 2;
            LDSM_X4(af[mt][0], af[mt][1], af[mt][2], af[mt][3], ah_b + aoff);
        }
#pragma unroll
        for (int mt = 0; mt < 2; mt++)
#pragma unroll
            for (int nt = 0; nt < 4; nt++) {
                MMA_BF16(acc[mt][nt], af[mt], bh[nt]);
                MMA_BF16(acc[mt][nt], af[mt], bl[nt]);
            }
#pragma unroll
        for (int mt = 0; mt < 2; mt++) {
            uint32_t aoff = (uint32_t)((wm + mt * 16 + l16) * LDP + k0 + lk * 8) * 2;
            LDSM_X4(af[mt][0], af[mt][1], af[mt][2], af[mt][3], al_b + aoff);
        }
#pragma unroll
        for (int mt = 0; mt < 2; mt++)
#pragma unroll
            for (int nt = 0; nt < 4; nt++)
                MMA_BF16(acc[mt][nt], af[mt], bh[nt]);
    }
}

// ---- single-fp16 chunk (output gemms) -------------------------------------
__device__ __forceinline__ void mma_chunk1(float acc[2][4][4],
    uint32_t a_b, uint32_t b_b, int wm, int wn, int lane)
{
    const int l16 = lane & 15, lk = lane >> 4;
    const int bn = ((lane >> 4) << 3) + (lane & 7);
    const int bk = ((lane >> 3) & 1) << 3;
#pragma unroll
    for (int ks = 0; ks < 4; ks++) {
        const int k0 = ks << 4;
        uint32_t bf[4][2], af[2][4];
#pragma unroll
        for (int g = 0; g < 2; g++) {
            uint32_t boff = (uint32_t)((wn + g * 16 + bn) * LDP + k0 + bk) * 2;
            LDSM_X4(bf[2*g][0], bf[2*g][1], bf[2*g+1][0], bf[2*g+1][1], b_b + boff);
        }
#pragma unroll
        for (int mt = 0; mt < 2; mt++) {
            uint32_t aoff = (uint32_t)((wm + mt * 16 + l16) * LDP + k0 + lk * 8) * 2;
            LDSM_X4(af[mt][0], af[mt][1], af[mt][2], af[mt][3], a_b + aoff);
        }
#pragma unroll
        for (int mt = 0; mt < 2; mt++)
#pragma unroll
            for (int nt = 0; nt < 4; nt++)
                MMA_FP16(acc[mt][nt], af[mt], bf[nt]);
    }
}

// ===========================================================================
// Kernel 0: prep — q,a -> bf16 hi/lo + fp16 caches
// ===========================================================================
__global__ void __launch_bounds__(256) prep_kernel(
    const float4* __restrict__ q4, const float4* __restrict__ a4)
{
    int idx = blockIdx.x * 256 + threadIdx.x;
    int isA = idx >> 22;
    int base = idx & 4194303;
    float4 v = (isA ? a4 : q4)[base];
    uint32_t h01, l01, h23, l23;
    split2(v.x, v.y, h01, l01);
    split2(v.z, v.w, h23, l23);
    uint2* dh = reinterpret_cast<uint2*>(isA ? g_ah : g_qh);
    uint2* dl = reinterpret_cast<uint2*>(isA ? g_al : g_ql);
    uint2* de = reinterpret_cast<uint2*>(isA ? g_ae : g_qe);
    dh[base] = make_uint2(h01, h23);
    dl[base] = make_uint2(l01, l23);
    de[base] = make_uint2(pack_h2(v.x, v.y), pack_h2(v.z, v.w));
}

// ===========================================================================
// Kernel 1: S = mask(temp * q a^T) — bf16x3, tile 128x128, K=512
// ===========================================================================
__global__ void __launch_bounds__(512, 1) score_tc(
    const int* __restrict__ qm, const int* __restrict__ am,
    const float* __restrict__ temp)
{
    extern __shared__ char sm[];
    __shared__ int s_qm[128], s_am[128];

    const int tid = threadIdx.x, lane = tid & 31, wid = tid >> 5;
    const int wm = (wid & 3) * 32, wn = (wid >> 2) * 32;
    const int b = blockIdx.z, m0 = blockIdx.y << 7, n0 = blockIdx.x << 7;

    if (tid < 128) { s_qm[tid] = qm[b * Ll + m0 + tid]; s_am[tid] = am[b * Ll + n0 + tid]; }

    const size_t qoff = ((size_t)b * Ll + m0) * Hh;
    const size_t aoff = ((size_t)b * Ll + n0) * Hh;

    uint2 vah[4], val_[4], vbh[4], vbl[4];
    ldg_c(vah, val_, g_qh + qoff, g_ql + qoff, Hh, 0, tid);
    ldg_c(vbh, vbl, g_ah + aoff, g_al + aoff, Hh, 0, tid);
    st_c(vah, val_, sm, sm + TILE_B, tid);
    st_c(vbh, vbl, sm + 2 * TILE_B, sm + 3 * TILE_B, tid);
    __syncthreads();

    float acc[2][4][4] = {};
    for (int kc = 0; kc < 8; kc++) {
        int nk = kc + 1;
        if (nk < 8) {
            ldg_c(vah, val_, g_qh + qoff, g_ql + qoff, Hh, nk << 6, tid);
            ldg_c(vbh, vbl, g_ah + aoff, g_al + aoff, Hh, nk << 6, tid);
        }
        char* cur = sm + (kc & 1) * BUF4_B;
        mma_chunk3(acc, s2u(cur), s2u(cur + TILE_B), s2u(cur + 2 * TILE_B),
                   s2u(cur + 3 * TILE_B), wm, wn, lane);
        if (nk < 8) {
            char* nb = sm + (nk & 1) * BUF4_B;
            st_c(vah, val_, nb, nb + TILE_B, tid);
            st_c(vbh, vbl, nb + 2 * TILE_B, nb + 3 * TILE_B, tid);
        }
        __syncthreads();
    }

    const float t = *temp;
#pragma unroll
    for (int mt = 0; mt < 2; mt++)
#pragma unroll
        for (int h2 = 0; h2 < 2; h2++) {
            int mloc = wm + mt * 16 + (lane >> 2) + h2 * 8;
            int qv = s_qm[mloc];
            float* row = g_S + ((size_t)b * Ll + m0 + mloc) * Ll + n0 + wn + (lane & 3) * 2;
#pragma unroll
            for (int nt = 0; nt < 4; nt++) {
                int c = wn + nt * 8 + (lane & 3) * 2;
                float2 v;
                v.x = (qv && s_am[c])     ? acc[mt][nt][h2 * 2]     * t : NEG_INF_V;
                v.y = (qv && s_am[c + 1]) ? acc[mt][nt][h2 * 2 + 1] * t : NEG_INF_V;
                *reinterpret_cast<float2*>(row + nt * 8) = v;
            }
        }
}

// ===========================================================================
// Kernel 2: per-row (axis=2) stats
// ===========================================================================
__global__ void __launch_bounds__(128) rowstats_kernel()
{
    const int row = blockIdx.x;
    const float* Sr = g_S + (size_t)row * Ll;
    const int tid = threadIdx.x;

    float v[8];
    float m = -3.4e38f;
#pragma unroll
    for (int i = 0; i < 8; i++) { v[i] = Sr[i * 128 + tid]; m = fmaxf(m, v[i]); }
#pragma unroll
    for (int o = 16; o; o >>= 1) m = fmaxf(m, __shfl_xor_sync(0xffffffffu, m, o));
    __shared__ float smx[4];
    if ((tid & 31) == 0) smx[tid >> 5] = m;
    __syncthreads();
    m = fmaxf(fmaxf(smx[0], smx[1]), fmaxf(smx[2], smx[3]));

    float s = 0.f;
#pragma unroll
    for (int i = 0; i < 8; i++) s += __expf(v[i] - m);
#pragma unroll
    for (int o = 16; o; o >>= 1) s += __shfl_xor_sync(0xffffffffu, s, o);
    __shared__ float ssm[4];
    if ((tid & 31) == 0) ssm[tid >> 5] = s;
    __syncthreads();
    if (tid == 0) { g_rowmax[row] = m; g_rowsum[row] = ssm[0] + ssm[1] + ssm[2] + ssm[3]; }
}

// ===========================================================================
// Kernel 3: per-column (axis=1) stats — 512 thr: 32 colgroups x 16 rowslices
// ===========================================================================
__global__ void __launch_bounds__(512) colstats_kernel()
{
    const int b = blockIdx.y;
    const int cg = threadIdx.x & 31;
    const int rs = threadIdx.x >> 5;     // 0..15
    const int c0 = blockIdx.x * 128 + cg * 4;
    const float* base = g_S + (size_t)b * Ll * Ll;
    __shared__ float4 red[512];

    float4 mx = make_float4(-3.4e38f, -3.4e38f, -3.4e38f, -3.4e38f);
    for (int r = rs * 64; r < rs * 64 + 64; r++) {
        float4 v = *reinterpret_cast<const float4*>(base + (size_t)r * Ll + c0);
        mx.x = fmaxf(mx.x, v.x); mx.y = fmaxf(mx.y, v.y);
        mx.z = fmaxf(mx.z, v.z); mx.w = fmaxf(mx.w, v.w);
    }
    red[threadIdx.x] = mx;
    __syncthreads();
    if (rs == 0) {
#pragma unroll
        for (int k = 1; k < 16; k++) {
            float4 o = red[k * 32 + cg];
            mx.x = fmaxf(mx.x, o.x); mx.y = fmaxf(mx.y, o.y);
            mx.z = fmaxf(mx.z, o.z); mx.w = fmaxf(mx.w, o.w);
        }
        red[cg] = mx;
    }
    __syncthreads();
    mx = red[cg];
    __syncthreads();

    float4 s4 = make_float4(0.f, 0.f, 0.f, 0.f);
    for (int r = rs * 64; r < rs * 64 + 64; r++) {
        float4 v = *reinterpret_cast<const float4*>(base + (size_t)r * Ll + c0);
        s4.x += __expf(v.x - mx.x); s4.y += __expf(v.y - mx.y);
        s4.z += __expf(v.z - mx.z); s4.w += __expf(v.w - mx.w);
    }
    red[threadIdx.x] = s4;
    __syncthreads();
    if (rs == 0) {
#pragma unroll
        for (int k = 1; k < 16; k++) {
            float4 o = red[k * 32 + cg];
            s4.x += o.x; s4.y += o.y; s4.z += o.z; s4.w += o.w;
        }
        *reinterpret_cast<float4*>(g_colmax + b * Ll + c0) = mx;
        *reinterpret_cast<float4*>(g_colsum + b * Ll + c0) = s4;
    }
}

// ===========================================================================
// Kernel 4: q_s = exp(S-rowmax) @ a / rowsum — fp16 single; copies q block
// ===========================================================================
__global__ void __launch_bounds__(512, 2) gemmQ_tc(
    const float4* __restrict__ q4, float* __restrict__ out)
{
    extern __shared__ char sm[];
    __shared__ float s_rm[128];

    const int tid = threadIdx.x, lane = tid & 31, wid = tid >> 5;
    const int wm = (wid & 3) * 32, wn = (wid >> 2) * 32;
    const int b = blockIdx.z, m0 = blockIdx.y << 7, n0 = blockIdx.x << 7;

    if (tid < 128) s_rm[tid] = g_rowmax[b * Ll + m0 + tid];
    __syncthreads();

    const float* Sb = g_S + (size_t)b * Ll * Ll + (size_t)m0 * Ll;
    const __half* ab = g_ae + (size_t)b * Ll * Hh + n0;

    float4 va[4];
    uint32_t vb[4][2];
    ldg_S(va, Sb, 0, tid);
    ldg_ht(vb, ab, Hh, tid);
    st_exp_h(va, sm, s_rm, tid);
    st_ht(vb, sm + TILE_B, tid);
    __syncthreads();

    float acc[2][4][4] = {};
    for (int kc = 0; kc < 16; kc++) {
        int nk = kc + 1;
        if (nk < 16) {
            ldg_S(va, Sb, nk << 6, tid);
            ldg_ht(vb, ab + (size_t)(nk << 6) * Hh, Hh, tid);
        }
        char* cur = sm + (kc & 1) * BUF2_B;
        mma_chunk1(acc, s2u(cur), s2u(cur + TILE_B), wm, wn, lane);
        if (nk < 16) {
            char* nb = sm + (nk & 1) * BUF2_B;
            st_exp_h(va, nb, s_rm, tid);
            st_ht(vb, nb + TILE_B, tid);
        }
        __syncthreads();
    }

#pragma unroll
    for (int mt = 0; mt < 2; mt++)
#pragma unroll
        for (int h2 = 0; h2 < 2; h2++) {
            int mloc = wm + mt * 16 + (lane >> 2) + h2 * 8;
            int m = m0 + mloc;
            float inv = 1.f / g_rowsum[b * Ll + m];
            float* row = out + ((size_t)b * Ll + m) * 1024 + 512 + n0 + wn + (lane & 3) * 2;
#pragma unroll
            for (int nt = 0; nt < 4; nt++) {
                float2 v;
                v.x = acc[mt][nt][h2 * 2] * inv;
                v.y = acc[mt][nt][h2 * 2 + 1] * inv;
                *reinterpret_cast<float2*>(row + nt * 8) = v;
            }
        }

    // copy q block into lower half
    float4* out4 = reinterpret_cast<float4*>(out);
#pragma unroll
    for (int i = 0; i < 8; i++) {
        int idx = (i << 9) + tid;
        int row = idx >> 5, c = idx & 31;
        size_t orow = (size_t)b * Ll + m0 + row;
        out4[orow * 256 + (n0 >> 2) + c] = q4[orow * 128 + (n0 >> 2) + c];
    }
}

// ===========================================================================
// Kernel 5: a_s = exp(S-colmax)^T @ q / colsum — fp16 single; copies a block
// ===========================================================================
__global__ void __launch_bounds__(512, 2) gemmA_tc(
    const float4* __restrict__ a4, float* __restrict__ out)
{
    extern __shared__ char sm[];
    __shared__ float s_cm[128];

    const int tid = threadIdx.x, lane = tid & 31, wid = tid >> 5;
    const int wm = (wid & 3) * 32, wn = (wid >> 2) * 32;
    const int b = blockIdx.z, m0 = blockIdx.y << 7, n0 = blockIdx.x << 7;

    if (tid < 128) s_cm[tid] = g_colmax[b * Ll + m0 + tid];
    __syncthreads();

    const float* Sb = g_S + (size_t)b * Ll * Ll + m0;     // S[k][m0+n]
    const __half* qb = g_qe + (size_t)b * Ll * Hh + n0;

    float4 va[4];
    uint32_t vb[4][2];
    ldg_St(va, Sb, tid);
    ldg_ht(vb, qb, Hh, tid);
    st_exp_h_t(va, sm, s_cm, tid);
    st_ht(vb, sm + TILE_B, tid);
    __syncthreads();

    float acc[2][4][4] = {};
    for (int kc = 0; kc < 16; kc++) {
        int nk = kc + 1;
        if (nk < 16) {
            ldg_St(va, Sb + (size_t)(nk << 6) * Ll, tid);
            ldg_ht(vb, qb + (size_t)(nk << 6) * Hh, Hh, tid);
        }
        char* cur = sm + (kc & 1) * BUF2_B;
        mma_chunk1(acc, s2u(cur), s2u(cur + TILE_B), wm, wn, lane);
        if (nk < 16) {
            char* nb = sm + (nk & 1) * BUF2_B;
            st_exp_h_t(va, nb, s_cm, tid);
            st_ht(vb, nb + TILE_B, tid);
        }
        __syncthreads();
    }

    const size_t OUT2 = (size_t)Bb * Ll * 1024;
#pragma unroll
    for (int mt = 0; mt < 2; mt++)
#pragma unroll
        for (int h2 = 0; h2 < 2; h2++) {
            int mloc = wm + mt * 16 + (lane >> 2) + h2 * 8;
            int m = m0 + mloc;
            float inv = 1.f / g_colsum[b * Ll + m];
            float* row = out + OUT2 + ((size_t)b * Ll + m) * 1024 + 512 + n0 + wn + (lane & 3) * 2;
#pragma unroll
            for (int nt = 0; nt < 4; nt++) {
                float2 v;
                v.x = acc[mt][nt][h2 * 2] * inv;
                v.y = acc[mt][nt][h2 * 2 + 1] * inv;
                *reinterpret_cast<float2*>(row + nt * 8) = v;
            }
        }

    // copy a block into lower half of out2
    float4* out4 = reinterpret_cast<float4*>(out + OUT2);
#pragma unroll
    for (int i = 0; i < 8; i++) {
        int idx = (i << 9) + tid;
        int row = idx >> 5, c = idx & 31;
        size_t orow = (size_t)b * Ll + m0 + row;
        out4[orow * 256 + (n0 >> 2) + c] = a4[orow * 128 + (n0 >> 2) + c];
    }
}

// ===========================================================================
extern "C" void kernel_launch(void* const* d_in, const int* in_sizes, int n_in,
                              void* d_out, int out_size)
{
    const float* q    = (const float*)d_in[0];
    const float* a    = (const float*)d_in[1];
    const int*   qm   = (const int*)  d_in[2];
    const int*   am   = (const int*)  d_in[3];
    const float* temp = (const float*)d_in[4];
    float* out = (float*)d_out;

    const int DS4 = 2 * BUF4_B;   // 147456 (score)
    const int DS2 = 2 * BUF2_B;   // 73728  (gemms)
    cudaFuncSetAttribute(score_tc, cudaFuncAttributeMaxDynamicSharedMemorySize, DS4);
    cudaFuncSetAttribute(gemmQ_tc, cudaFuncAttributeMaxDynamicSharedMemorySize, DS2);
    cudaFuncSetAttribute(gemmA_tc, cudaFuncAttributeMaxDynamicSharedMemorySize, DS2);

    prep_kernel<<<32768, 256>>>((const float4*)q, (const float4*)a);
    score_tc<<<dim3(8, 8, 32), 512, DS4>>>(qm, am, temp);
    rowstats_kernel<<<Bb * Ll, 128>>>();
    colstats_kernel<<<dim3(8, 32), 512>>>();
    gemmQ_tc<<<dim3(4, 8, 32), 512, DS2>>>((const float4*)q, out);
    gemmA_tc<<<dim3(4, 8, 32), 512, DS2>>>((const float4*)a, out);
}

// round 12
// speedup vs baseline: 1.9420x; 1.4031x over previous
#include <cuda_runtime.h>
#include <cuda_fp16.h>
#include <cstdint>

#define Bb 32
#define Ll 1024
#define Hh 512

// Scratch
__device__ __half g_P[(size_t)Bb * Ll * Ll];      // exp(t*S) masked, fp16, 64 MB
__device__ float  g_rowsum[Bb * Ll];
__device__ float  g_colsum[Bb * Ll];
__device__ float  g_qbar[Bb * Hh];                // per-batch mean of q over l
__device__ float  g_abar[Bb * Hh];                // per-batch mean of a over l
__device__ __half g_qe[16777216], g_ae[16777216]; // fp16 operand caches

// ---------------------------------------------------------------------------
__device__ __forceinline__ uint32_t s2u(const void* p) {
    uint32_t a;
    asm("{ .reg .u64 t; cvta.to.shared.u64 t, %1; cvt.u32.u64 %0, t; }" : "=r"(a) : "l"(p));
    return a;
}
#define LDSM_X4(r0, r1, r2, r3, addr)                                        \
    asm volatile("ldmatrix.sync.aligned.m8n8.x4.shared.b16 {%0,%1,%2,%3}, [%4];" \
                 : "=r"(r0), "=r"(r1), "=r"(r2), "=r"(r3) : "r"(addr))
#define MMA_FP16(c, a, b)                                                    \
    asm volatile("mma.sync.aligned.m16n8k16.row.col.f32.f16.f16.f32 "        \
                 "{%0,%1,%2,%3}, {%4,%5,%6,%7}, {%8,%9}, {%0,%1,%2,%3};"     \
                 : "+f"((c)[0]), "+f"((c)[1]), "+f"((c)[2]), "+f"((c)[3])    \
                 : "r"((a)[0]), "r"((a)[1]), "r"((a)[2]), "r"((a)[3]),       \
                   "r"((b)[0]), "r"((b)[1]))

__device__ __forceinline__ uint32_t pack_h2(float x0, float x1) {
    __half2 h = __floats2half2_rn(x0, x1);
    return reinterpret_cast<uint32_t&>(h);
}

#define LDP 72
#define TILE_B 18432              // 128 rows x 72 halves x 2B
#define BUF2_B (2 * TILE_B)       // A + B tiles per stage

// ===== fp16 tile loaders (512 threads) =====================================
// contiguous (k-major): tile[128 rows][64 k] from src[row*ld + k0 + k]
__device__ __forceinline__ void ldg_h(uint2 v[4],
    const __half* __restrict__ src, int ld, int k0, int tid)
{
#pragma unroll
    for (int i = 0; i < 4; i++) {
        int idx = (i << 9) + tid;
        int row = idx >> 4, c4 = idx & 15;
        v[i] = *reinterpret_cast<const uint2*>(src + (size_t)row * ld + k0 + (c4 << 2));
    }
}
__device__ __forceinline__ void st_h(const uint2 v[4], char* d, int tid)
{
#pragma unroll
    for (int i = 0; i < 4; i++) {
        int idx = (i << 9) + tid;
        int row = idx >> 4, c4 = idx & 15;
        uint32_t off = (uint32_t)(row * LDP + (c4 << 2)) * 2;
        *reinterpret_cast<uint2*>(d + off) = v[i];
    }
}
// transposed: tile[n=128][k=64] from src[k*ld + n]
__device__ __forceinline__ void ldg_ht(uint32_t v[4][2],
    const __half* __restrict__ src, int ld, int tid)
{
#pragma unroll
    for (int i = 0; i < 4; i++) {
        int idx = (i << 9) + tid;
        int n = idx & 127, k4 = idx >> 7;
        const ushort* h0 = (const ushort*)src + (size_t)(k4 << 2) * ld + n;
        v[i][0] = (uint32_t)h0[0] | ((uint32_t)h0[ld] << 16);
        v[i][1] = (uint32_t)h0[2 * (size_t)ld] | ((uint32_t)h0[3 * (size_t)ld] << 16);
    }
}
__device__ __forceinline__ void st_ht(const uint32_t v[4][2], char* d, int tid)
{
#pragma unroll
    for (int i = 0; i < 4; i++) {
        int idx = (i << 9) + tid;
        int n = idx & 127, k4 = idx >> 7;
        uint32_t off = (uint32_t)(n * LDP + (k4 << 2)) * 2;
        *reinterpret_cast<uint2*>(d + off) = make_uint2(v[i][0], v[i][1]);
    }
}

// ---- fp16 chunk: warp tile 32(M) x 32(N), K=64 ----------------------------
__device__ __forceinline__ void mma_chunk1(float acc[2][4][4],
    uint32_t a_b, uint32_t b_b, int wm, int wn, int lane)
{
    const int l16 = lane & 15, lk = lane >> 4;
    const int bn = ((lane >> 4) << 3) + (lane & 7);
    const int bk = ((lane >> 3) & 1) << 3;
#pragma unroll
    for (int ks = 0; ks < 4; ks++) {
        const int k0 = ks << 4;
        uint32_t bf[4][2], af[2][4];
#pragma unroll
        for (int g = 0; g < 2; g++) {
            uint32_t boff = (uint32_t)((wn + g * 16 + bn) * LDP + k0 + bk) * 2;
            LDSM_X4(bf[2*g][0], bf[2*g][1], bf[2*g+1][0], bf[2*g+1][1], b_b + boff);
        }
#pragma unroll
        for (int mt = 0; mt < 2; mt++) {
            uint32_t aoff = (uint32_t)((wm + mt * 16 + l16) * LDP + k0 + lk * 8) * 2;
            LDSM_X4(af[mt][0], af[mt][1], af[mt][2], af[mt][3], a_b + aoff);
        }
#pragma unroll
        for (int mt = 0; mt < 2; mt++)
#pragma unroll
            for (int nt = 0; nt < 4; nt++)
                MMA_FP16(acc[mt][nt], af[mt], bf[nt]);
    }
}

// ===========================================================================
// Kernel 0: prep — q,a -> fp16 caches
// ===========================================================================
__global__ void __launch_bounds__(256) prep_kernel(
    const float4* __restrict__ q4, const float4* __restrict__ a4)
{
    int idx = blockIdx.x * 256 + threadIdx.x;
    int isA = idx >> 22;
    int base = idx & 4194303;
    float4 v = (isA ? a4 : q4)[base];
    uint2* de = reinterpret_cast<uint2*>(isA ? g_ae : g_qe);
    de[base] = make_uint2(pack_h2(v.x, v.y), pack_h2(v.z, v.w));
}

// ===========================================================================
// Kernel 0b: per-batch column means of q and a (uniform-softmax fallback)
// grid (2, 32, 2) block (256, 4)
// ===========================================================================
__global__ void means_kernel(const float* __restrict__ q, const float* __restrict__ a)
{
    const float* src = blockIdx.z ? a : q;
    float* dst = blockIdx.z ? g_abar : g_qbar;
    const int b = blockIdx.y;
    const int h = blockIdx.x * 256 + threadIdx.x;
    float s = 0.f;
    const int r0 = threadIdx.y * 256;
    const float* p = src + ((size_t)b * Ll + r0) * Hh + h;
    for (int r = 0; r < 256; r++) s += p[(size_t)r * Hh];
    __shared__ float red[4][256];
    red[threadIdx.y][threadIdx.x] = s;
    __syncthreads();
    if (threadIdx.y == 0) {
        float t = red[0][threadIdx.x] + red[1][threadIdx.x]
                + red[2][threadIdx.x] + red[3][threadIdx.x];
        dst[b * Hh + h] = t * (1.0f / 1024.0f);
    }
}

// ===========================================================================
// Kernel 1: P = exp(temp * q a^T) masked (0 where invalid) — fp16 MMA + exp
// ===========================================================================
__global__ void __launch_bounds__(512, 2) score_h(
    const int* __restrict__ qm, const int* __restrict__ am,
    const float* __restrict__ temp)
{
    extern __shared__ char sm[];
    __shared__ int s_qm[128], s_am[128];

    const int tid = threadIdx.x, lane = tid & 31, wid = tid >> 5;
    const int wm = (wid & 3) * 32, wn = (wid >> 2) * 32;
    const int b = blockIdx.z, m0 = blockIdx.y << 7, n0 = blockIdx.x << 7;

    if (tid < 128) { s_qm[tid] = qm[b * Ll + m0 + tid]; s_am[tid] = am[b * Ll + n0 + tid]; }

    const __half* qb = g_qe + ((size_t)b * Ll + m0) * Hh;
    const __half* ab = g_ae + ((size_t)b * Ll + n0) * Hh;

    uint2 va[4], vb[4];
    ldg_h(va, qb, Hh, 0, tid);
    ldg_h(vb, ab, Hh, 0, tid);
    st_h(va, sm, tid);
    st_h(vb, sm + TILE_B, tid);
    __syncthreads();

    float acc[2][4][4] = {};
    for (int kc = 0; kc < 8; kc++) {
        int nk = kc + 1;
        if (nk < 8) {
            ldg_h(va, qb, Hh, nk << 6, tid);
            ldg_h(vb, ab, Hh, nk << 6, tid);
        }
        char* cur = sm + (kc & 1) * BUF2_B;
        mma_chunk1(acc, s2u(cur), s2u(cur + TILE_B), wm, wn, lane);
        if (nk < 8) {
            char* nb = sm + (nk & 1) * BUF2_B;
            st_h(va, nb, tid);
            st_h(vb, nb + TILE_B, tid);
        }
        __syncthreads();
    }

    const float t = *temp;
#pragma unroll
    for (int mt = 0; mt < 2; mt++)
#pragma unroll
        for (int h2 = 0; h2 < 2; h2++) {
            int mloc = wm + mt * 16 + (lane >> 2) + h2 * 8;
            int qv = s_qm[mloc];
            ushort* row = (ushort*)g_P + ((size_t)b * Ll + m0 + mloc) * Ll
                        + n0 + wn + (lane & 3) * 2;
#pragma unroll
            for (int nt = 0; nt < 4; nt++) {
                int c = wn + nt * 8 + (lane & 3) * 2;
                float e0 = (qv && s_am[c])     ? __expf(acc[mt][nt][h2 * 2]     * t) : 0.f;
                float e1 = (qv && s_am[c + 1]) ? __expf(acc[mt][nt][h2 * 2 + 1] * t) : 0.f;
                *reinterpret_cast<uint32_t*>(row + nt * 8) = pack_h2(e0, e1);
            }
        }
}

// ===========================================================================
// Kernel 2: row sums of P (axis=2)  — one block per row
// ===========================================================================
__global__ void __launch_bounds__(128) rowsum_kernel()
{
    const int row = blockIdx.x;
    const int tid = threadIdx.x;
    const uint4 u = *reinterpret_cast<const uint4*>((const ushort*)g_P + (size_t)row * Ll + tid * 8);
    float s = 0.f;
    {
        __half2 h0 = *reinterpret_cast<const __half2*>(&u.x);
        __half2 h1 = *reinterpret_cast<const __half2*>(&u.y);
        __half2 h2 = *reinterpret_cast<const __half2*>(&u.z);
        __half2 h3 = *reinterpret_cast<const __half2*>(&u.w);
        float2 f0 = __half22float2(h0), f1 = __half22float2(h1);
        float2 f2 = __half22float2(h2), f3 = __half22float2(h3);
        s = f0.x + f0.y + f1.x + f1.y + f2.x + f2.y + f3.x + f3.y;
    }
#pragma unroll
    for (int o = 16; o; o >>= 1) s += __shfl_xor_sync(0xffffffffu, s, o);
    __shared__ float red[4];
    if ((tid & 31) == 0) red[tid >> 5] = s;
    __syncthreads();
    if (tid == 0) g_rowsum[row] = red[0] + red[1] + red[2] + red[3];
}

// ===========================================================================
// Kernel 3: col sums of P (axis=1) — block 512 = 32 colgroups(x8) x 16 slices
// grid (4, 32)
// ===========================================================================
__global__ void __launch_bounds__(512) colsum_kernel()
{
    const int b = blockIdx.y;
    const int cg = threadIdx.x & 31;
    const int rs = threadIdx.x >> 5;
    const int c0 = blockIdx.x * 256 + cg * 8;
    const ushort* base = (const ushort*)g_P + (size_t)b * Ll * Ll;
    __shared__ float red[512][8];

    float s[8] = {};
    for (int r = rs * 64; r < rs * 64 + 64; r++) {
        uint4 u = *reinterpret_cast<const uint4*>(base + (size_t)r * Ll + c0);
        float2 f0 = __half22float2(*reinterpret_cast<const __half2*>(&u.x));
        float2 f1 = __half22float2(*reinterpret_cast<const __half2*>(&u.y));
        float2 f2 = __half22float2(*reinterpret_cast<const __half2*>(&u.z));
        float2 f3 = __half22float2(*reinterpret_cast<const __half2*>(&u.w));
        s[0] += f0.x; s[1] += f0.y; s[2] += f1.x; s[3] += f1.y;
        s[4] += f2.x; s[5] += f2.y; s[6] += f3.x; s[7] += f3.y;
    }
#pragma unroll
    for (int j = 0; j < 8; j++) red[threadIdx.x][j] = s[j];
    __syncthreads();
    if (rs == 0) {
#pragma unroll
        for (int k = 1; k < 16; k++)
#pragma unroll
            for (int j = 0; j < 8; j++) s[j] += red[k * 32 + cg][j];
#pragma unroll
        for (int j = 0; j < 8; j++) g_colsum[b * Ll + c0 + j] = s[j];
    }
}

// ===========================================================================
// Kernel 4: q_s = P @ a / rowsum (abar fallback) — copies q block too
// ===========================================================================
__global__ void __launch_bounds__(512, 2) gemmQ_tc(
    const float4* __restrict__ q4, float* __restrict__ out)
{
    extern __shared__ char sm[];
    const int tid = threadIdx.x, lane = tid & 31, wid = tid >> 5;
    const int wm = (wid & 3) * 32, wn = (wid >> 2) * 32;
    const int b = blockIdx.z, m0 = blockIdx.y << 7, n0 = blockIdx.x << 7;

    const __half* Pb = g_P + ((size_t)b * Ll + m0) * Ll;
    const __half* ab = g_ae + (size_t)b * Ll * Hh + n0;

    uint2 va[4];
    uint32_t vb[4][2];
    ldg_h(va, Pb, Ll, 0, tid);
    ldg_ht(vb, ab, Hh, tid);
    st_h(va, sm, tid);
    st_ht(vb, sm + TILE_B, tid);
    __syncthreads();

    float acc[2][4][4] = {};
    for (int kc = 0; kc < 16; kc++) {
        int nk = kc + 1;
        if (nk < 16) {
            ldg_h(va, Pb, Ll, nk << 6, tid);
            ldg_ht(vb, ab + (size_t)(nk << 6) * Hh, Hh, tid);
        }
        char* cur = sm + (kc & 1) * BUF2_B;
        mma_chunk1(acc, s2u(cur), s2u(cur + TILE_B), wm, wn, lane);
        if (nk < 16) {
            char* nb = sm + (nk & 1) * BUF2_B;
            st_h(va, nb, tid);
            st_ht(vb, nb + TILE_B, tid);
        }
        __syncthreads();
    }

#pragma unroll
    for (int mt = 0; mt < 2; mt++)
#pragma unroll
        for (int h2 = 0; h2 < 2; h2++) {
            int mloc = wm + mt * 16 + (lane >> 2) + h2 * 8;
            int m = m0 + mloc;
            float rs = g_rowsum[b * Ll + m];
            float inv = (rs != 0.f) ? 1.f / rs : 0.f;
            const float* abar = g_abar + b * Hh + n0 + wn + (lane & 3) * 2;
            float* row = out + ((size_t)b * Ll + m) * 1024 + 512 + n0 + wn + (lane & 3) * 2;
#pragma unroll
            for (int nt = 0; nt < 4; nt++) {
                float2 v;
                float ab0 = abar[nt * 8], ab1 = abar[nt * 8 + 1];
                v.x = (rs != 0.f) ? acc[mt][nt][h2 * 2]     * inv : ab0;
                v.y = (rs != 0.f) ? acc[mt][nt][h2 * 2 + 1] * inv : ab1;
                *reinterpret_cast<float2*>(row + nt * 8) = v;
            }
        }

    // copy q block into lower half
    float4* out4 = reinterpret_cast<float4*>(out);
#pragma unroll
    for (int i = 0; i < 8; i++) {
        int idx = (i << 9) + tid;
        int row = idx >> 5, c = idx & 31;
        size_t orow = (size_t)b * Ll + m0 + row;
        out4[orow * 256 + (n0 >> 2) + c] = q4[orow * 128 + (n0 >> 2) + c];
    }
}

// ===========================================================================
// Kernel 5: a_s = P^T @ q / colsum (qbar fallback) — copies a block too
// ===========================================================================
__global__ void __launch_bounds__(512, 2) gemmA_tc(
    const float4* __restrict__ a4, float* __restrict__ out)
{
    extern __shared__ char sm[];
    const int tid = threadIdx.x, lane = tid & 31, wid = tid >> 5;
    const int wm = (wid & 3) * 32, wn = (wid >> 2) * 32;
    const int b = blockIdx.z, m0 = blockIdx.y << 7, n0 = blockIdx.x << 7;

    const __half* Pb = g_P + (size_t)b * Ll * Ll + m0;   // P[k=q][m0+n]
    const __half* qb = g_qe + (size_t)b * Ll * Hh + n0;

    uint32_t va[4][2], vb[4][2];
    ldg_ht(va, Pb, Ll, tid);
    ldg_ht(vb, qb, Hh, tid);
    st_ht(va, sm, tid);
    st_ht(vb, sm + TILE_B, tid);
    __syncthreads();

    float acc[2][4][4] = {};
    for (int kc = 0; kc < 16; kc++) {
        int nk = kc + 1;
        if (nk < 16) {
            ldg_ht(va, Pb + (size_t)(nk << 6) * Ll, Ll, tid);
            ldg_ht(vb, qb + (size_t)(nk << 6) * Hh, Hh, tid);
        }
        char* cur = sm + (kc & 1) * BUF2_B;
        mma_chunk1(acc, s2u(cur), s2u(cur + TILE_B), wm, wn, lane);
        if (nk < 16) {
            char* nb = sm + (nk & 1) * BUF2_B;
            st_ht(va, nb, tid);
            st_ht(vb, nb + TILE_B, tid);
        }
        __syncthreads();
    }

    const size_t OUT2 = (size_t)Bb * Ll * 1024;
#pragma unroll
    for (int mt = 0; mt < 2; mt++)
#pragma unroll
        for (int h2 = 0; h2 < 2; h2++) {
            int mloc = wm + mt * 16 + (lane >> 2) + h2 * 8;
            int m = m0 + mloc;
            float cs = g_colsum[b * Ll + m];
            float inv = (cs != 0.f) ? 1.f / cs : 0.f;
            const float* qbar = g_qbar + b * Hh + n0 + wn + (lane & 3) * 2;
            float* row = out + OUT2 + ((size_t)b * Ll + m) * 1024 + 512 + n0 + wn + (lane & 3) * 2;
#pragma unroll
            for (int nt = 0; nt < 4; nt++) {
                float2 v;
                float qb0 = qbar[nt * 8], qb1 = qbar[nt * 8 + 1];
                v.x = (cs != 0.f) ? acc[mt][nt][h2 * 2]     * inv : qb0;
                v.y = (cs != 0.f) ? acc[mt][nt][h2 * 2 + 1] * inv : qb1;
                *reinterpret_cast<float2*>(row + nt * 8) = v;
            }
        }

    // copy a block into lower half of out2
    float4* out4 = reinterpret_cast<float4*>(out + OUT2);
#pragma unroll
    for (int i = 0; i < 8; i++) {
        int idx = (i << 9) + tid;
        int row = idx >> 5, c = idx & 31;
        size_t orow = (size_t)b * Ll + m0 + row;
        out4[orow * 256 + (n0 >> 2) + c] = a4[orow * 128 + (n0 >> 2) + c];
    }
}

// ===========================================================================
extern "C" void kernel_launch(void* const* d_in, const int* in_sizes, int n_in,
                              void* d_out, int out_size)
{
    const float* q    = (const float*)d_in[0];
    const float* a    = (const float*)d_in[1];
    const int*   qm   = (const int*)  d_in[2];
    const int*   am   = (const int*)  d_in[3];
    const float* temp = (const float*)d_in[4];
    float* out = (float*)d_out;

    const int DS2 = 2 * BUF2_B;   // 73728
    cudaFuncSetAttribute(score_h,  cudaFuncAttributeMaxDynamicSharedMemorySize, DS2);
    cudaFuncSetAttribute(gemmQ_tc, cudaFuncAttributeMaxDynamicSharedMemorySize, DS2);
    cudaFuncSetAttribute(gemmA_tc, cudaFuncAttributeMaxDynamicSharedMemorySize, DS2);

    prep_kernel<<<32768, 256>>>((const float4*)q, (const float4*)a);
    means_kernel<<<dim3(2, 32, 2), dim3(256, 4)>>>(q, a);
    score_h<<<dim3(8, 8, 32), 512, DS2>>>(qm, am, temp);
    rowsum_kernel<<<Bb * Ll, 128>>>();
    colsum_kernel<<<dim3(4, 32), 512>>>();
    gemmQ_tc<<<dim3(4, 8, 32), 512, DS2>>>((const float4*)q, out);
    gemmA_tc<<<dim3(4, 8, 32), 512, DS2>>>((const float4*)a, out);
}

// round 14
// speedup vs baseline: 1.9489x; 1.0036x over previous
#include <cuda_runtime.h>
#include <cuda_fp16.h>
#include <cstdint>

#define Bb 32
#define Ll 1024
#define Hh 512

// Scratch
__device__ __half g_P[(size_t)Bb * Ll * Ll];      // exp(t*S) masked, fp16, 64 MB
__device__ float  g_rowsum[Bb * Ll];
__device__ float  g_colsum[Bb * Ll];
__device__ float  g_qbar[Bb * Hh];                // per-batch mean of q over l
__device__ float  g_abar[Bb * Hh];                // per-batch mean of a over l
__device__ __half g_qe[16777216], g_ae[16777216]; // fp16 operand caches

// ---------------------------------------------------------------------------
__device__ __forceinline__ uint32_t s2u(const void* p) {
    uint32_t a;
    asm("{ .reg .u64 t; cvta.to.shared.u64 t, %1; cvt.u32.u64 %0, t; }" : "=r"(a) : "l"(p));
    return a;
}
#define LDSM_X4(r0, r1, r2, r3, addr)                                        \
    asm volatile("ldmatrix.sync.aligned.m8n8.x4.shared.b16 {%0,%1,%2,%3}, [%4];" \
                 : "=r"(r0), "=r"(r1), "=r"(r2), "=r"(r3) : "r"(addr))
#define MMA_FP16(c, a, b)                                                    \
    asm volatile("mma.sync.aligned.m16n8k16.row.col.f32.f16.f16.f32 "        \
                 "{%0,%1,%2,%3}, {%4,%5,%6,%7}, {%8,%9}, {%0,%1,%2,%3};"     \
                 : "+f"((c)[0]), "+f"((c)[1]), "+f"((c)[2]), "+f"((c)[3])    \
                 : "r"((a)[0]), "r"((a)[1]), "r"((a)[2]), "r"((a)[3]),       \
                   "r"((b)[0]), "r"((b)[1]))

__device__ __forceinline__ uint32_t pack_h2(float x0, float x1) {
    __half2 h = __floats2half2_rn(x0, x1);
    return reinterpret_cast<uint32_t&>(h);
}

#define LDP 72
#define TILE_B 18432              // 128 rows x 72 halves x 2B
#define BUF2_B (2 * TILE_B)       // A + B tiles per stage

// ===== fp16 tile loaders (512 threads) =====================================
__device__ __forceinline__ void ldg_h(uint2 v[4],
    const __half* __restrict__ src, int ld, int k0, int tid)
{
#pragma unroll
    for (int i = 0; i < 4; i++) {
        int idx = (i << 9) + tid;
        int row = idx >> 4, c4 = idx & 15;
        v[i] = *reinterpret_cast<const uint2*>(src + (size_t)row * ld + k0 + (c4 << 2));
    }
}
__device__ __forceinline__ void st_h(const uint2 v[4], char* d, int tid)
{
#pragma unroll
    for (int i = 0; i < 4; i++) {
        int idx = (i << 9) + tid;
        int row = idx >> 4, c4 = idx & 15;
        uint32_t off = (uint32_t)(row * LDP + (c4 << 2)) * 2;
        *reinterpret_cast<uint2*>(d + off) = v[i];
    }
}
__device__ __forceinline__ void ldg_ht(uint32_t v[4][2],
    const __half* __restrict__ src, int ld, int tid)
{
#pragma unroll
    for (int i = 0; i < 4; i++) {
        int idx = (i << 9) + tid;
        int n = idx & 127, k4 = idx >> 7;
        const ushort* h0 = (const ushort*)src + (size_t)(k4 << 2) * ld + n;
        v[i][0] = (uint32_t)h0[0] | ((uint32_t)h0[ld] << 16);
        v[i][1] = (uint32_t)h0[2 * (size_t)ld] | ((uint32_t)h0[3 * (size_t)ld] << 16);
    }
}
__device__ __forceinline__ void st_ht(const uint32_t v[4][2], char* d, int tid)
{
#pragma unroll
    for (int i = 0; i < 4; i++) {
        int idx = (i << 9) + tid;
        int n = idx & 127, k4 = idx >> 7;
        uint32_t off = (uint32_t)(n * LDP + (k4 << 2)) * 2;
        *reinterpret_cast<uint2*>(d + off) = make_uint2(v[i][0], v[i][1]);
    }
}

// ---- fp16 chunk: warp tile 32(M) x 32(N), K=64 ----------------------------
__device__ __forceinline__ void mma_chunk1(float acc[2][4][4],
    uint32_t a_b, uint32_t b_b, int wm, int wn, int lane)
{
    const int l16 = lane & 15, lk = lane >> 4;
    const int bn = ((lane >> 4) << 3) + (lane & 7);
    const int bk = ((lane >> 3) & 1) << 3;
#pragma unroll
    for (int ks = 0; ks < 4; ks++) {
        const int k0 = ks << 4;
        uint32_t bf[4][2], af[2][4];
#pragma unroll
        for (int g = 0; g < 2; g++) {
            uint32_t boff = (uint32_t)((wn + g * 16 + bn) * LDP + k0 + bk) * 2;
            LDSM_X4(bf[2*g][0], bf[2*g][1], bf[2*g+1][0], bf[2*g+1][1], b_b + boff);
        }
#pragma unroll
        for (int mt = 0; mt < 2; mt++) {
            uint32_t aoff = (uint32_t)((wm + mt * 16 + l16) * LDP + k0 + lk * 8) * 2;
            LDSM_X4(af[mt][0], af[mt][1], af[mt][2], af[mt][3], a_b + aoff);
        }
#pragma unroll
        for (int mt = 0; mt < 2; mt++)
#pragma unroll
            for (int nt = 0; nt < 4; nt++)
                MMA_FP16(acc[mt][nt], af[mt], bf[nt]);
    }
}

// ===========================================================================
// Kernel 0: prep — q,a -> fp16 caches; zeroes the atomic sum arrays
// ===========================================================================
__global__ void __launch_bounds__(256) prep_kernel(
    const float4* __restrict__ q4, const float4* __restrict__ a4)
{
    int idx = blockIdx.x * 256 + threadIdx.x;
    if (idx < Bb * Ll) { g_rowsum[idx] = 0.f; g_colsum[idx] = 0.f; }
    int isA = idx >> 22;
    int base = idx & 4194303;
    float4 v = (isA ? a4 : q4)[base];
    uint2* de = reinterpret_cast<uint2*>(isA ? g_ae : g_qe);
    de[base] = make_uint2(pack_h2(v.x, v.y), pack_h2(v.z, v.w));
}

// ===========================================================================
// Kernel 0b: per-batch column means of q and a (uniform-softmax fallback)
// ===========================================================================
__global__ void means_kernel(const float* __restrict__ q, const float* __restrict__ a)
{
    const float* src = blockIdx.z ? a : q;
    float* dst = blockIdx.z ? g_abar : g_qbar;
    const int b = blockIdx.y;
    const int h = blockIdx.x * 256 + threadIdx.x;
    float s = 0.f;
    const int r0 = threadIdx.y * 256;
    const float* p = src + ((size_t)b * Ll + r0) * Hh + h;
    for (int r = 0; r < 256; r++) s += p[(size_t)r * Hh];
    __shared__ float red[4][256];
    red[threadIdx.y][threadIdx.x] = s;
    __syncthreads();
    if (threadIdx.y == 0) {
        float t = red[0][threadIdx.x] + red[1][threadIdx.x]
                + red[2][threadIdx.x] + red[3][threadIdx.x];
        dst[b * Hh + h] = t * (1.0f / 1024.0f);
    }
}

// ===========================================================================
// Kernel 1: P = exp(temp * q a^T) masked + fused row/col partial sums
// ===========================================================================
__global__ void __launch_bounds__(512, 2) score_h(
    const int* __restrict__ qm, const int* __restrict__ am,
    const float* __restrict__ temp)
{
    extern __shared__ char sm[];
    __shared__ int s_qm[128], s_am[128];
    __shared__ float srow[128], scol[128];

    const int tid = threadIdx.x, lane = tid & 31, wid = tid >> 5;
    const int wm = (wid & 3) * 32, wn = (wid >> 2) * 32;
    const int b = blockIdx.z, m0 = blockIdx.y << 7, n0 = blockIdx.x << 7;

    if (tid < 128) {
        s_qm[tid] = qm[b * Ll + m0 + tid];
        s_am[tid] = am[b * Ll + n0 + tid];
        srow[tid] = 0.f;
        scol[tid] = 0.f;
    }

    const __half* qb = g_qe + ((size_t)b * Ll + m0) * Hh;
    const __half* ab = g_ae + ((size_t)b * Ll + n0) * Hh;

    uint2 va[4], vb[4];
    ldg_h(va, qb, Hh, 0, tid);
    ldg_h(vb, ab, Hh, 0, tid);
    st_h(va, sm, tid);
    st_h(vb, sm + TILE_B, tid);
    __syncthreads();

    float acc[2][4][4] = {};
    for (int kc = 0; kc < 8; kc++) {
        int nk = kc + 1;
        if (nk < 8) {
            ldg_h(va, qb, Hh, nk << 6, tid);
            ldg_h(vb, ab, Hh, nk << 6, tid);
        }
        char* cur = sm + (kc & 1) * BUF2_B;
        mma_chunk1(acc, s2u(cur), s2u(cur + TILE_B), wm, wn, lane);
        if (nk < 8) {
            char* nb = sm + (nk & 1) * BUF2_B;
            st_h(va, nb, tid);
            st_h(vb, nb + TILE_B, tid);
        }
        __syncthreads();
    }

    const float t = *temp;
    float cp[4][2] = {};
#pragma unroll
    for (int mt = 0; mt < 2; mt++)
#pragma unroll
        for (int h2 = 0; h2 < 2; h2++) {
            int mloc = wm + mt * 16 + (lane >> 2) + h2 * 8;
            int qv = s_qm[mloc];
            ushort* row = (ushort*)g_P + ((size_t)b * Ll + m0 + mloc) * Ll
                        + n0 + wn + (lane & 3) * 2;
            float rp = 0.f;
#pragma unroll
            for (int nt = 0; nt < 4; nt++) {
                int c = wn + nt * 8 + (lane & 3) * 2;
                float e0 = (qv && s_am[c])     ? __expf(acc[mt][nt][h2 * 2]     * t) : 0.f;
                float e1 = (qv && s_am[c + 1]) ? __expf(acc[mt][nt][h2 * 2 + 1] * t) : 0.f;
                uint32_t pk = pack_h2(e0, e1);
                *reinterpret_cast<uint32_t*>(row + nt * 8) = pk;
                // sums from the quantized values (self-consistent with gemm reads)
                float2 f = __half22float2(*reinterpret_cast<__half2*>(&pk));
                rp += f.x + f.y;
                cp[nt][0] += f.x;
                cp[nt][1] += f.y;
            }
            atomicAdd(&srow[mloc], rp);
        }
#pragma unroll
    for (int nt = 0; nt < 4; nt++) {
        int c = wn + nt * 8 + (lane & 3) * 2;
        atomicAdd(&scol[c], cp[nt][0]);
        atomicAdd(&scol[c + 1], cp[nt][1]);
    }
    __syncthreads();
    if (tid < 128) {
        atomicAdd(&g_rowsum[b * Ll + m0 + tid], srow[tid]);
        atomicAdd(&g_colsum[b * Ll + n0 + tid], scol[tid]);
    }
}

// ===========================================================================
// Kernel 2: fused output GEMMs. z<32: q_s = P @ a / rowsum (+copy q)
//                              z>=32: a_s = P^T @ q / colsum (+copy a)
// ===========================================================================
__global__ void __launch_bounds__(512, 2) gemm_fused(
    const float4* __restrict__ q4, const float4* __restrict__ a4,
    float* __restrict__ out)
{
    extern __shared__ char sm[];
    const int tid = threadIdx.x, lane = tid & 31, wid = tid >> 5;
    const int wm = (wid & 3) * 32, wn = (wid >> 2) * 32;
    const int z = blockIdx.z;
    const int isA = z >> 5;
    const int b = z & 31;
    const int m0 = blockIdx.y << 7, n0 = blockIdx.x << 7;

    float acc[2][4][4] = {};

    if (!isA) {
        // ---- Q side: A = P (k-major), B = a (transposed) ----
        const __half* Pb = g_P + ((size_t)b * Ll + m0) * Ll;
        const __half* ab = g_ae + (size_t)b * Ll * Hh + n0;

        uint2 va[4];
        uint32_t vb[4][2];
        ldg_h(va, Pb, Ll, 0, tid);
        ldg_ht(vb, ab, Hh, tid);
        st_h(va, sm, tid);
        st_ht(vb, sm + TILE_B, tid);
        __syncthreads();

        for (int kc = 0; kc < 16; kc++) {
            int nk = kc + 1;
            if (nk < 16) {
                ldg_h(va, Pb, Ll, nk << 6, tid);
                ldg_ht(vb, ab + (size_t)(nk << 6) * Hh, Hh, tid);
            }
            char* cur = sm + (kc & 1) * BUF2_B;
            mma_chunk1(acc, s2u(cur), s2u(cur + TILE_B), wm, wn, lane);
            if (nk < 16) {
                char* nb = sm + (nk & 1) * BUF2_B;
                st_h(va, nb, tid);
                st_ht(vb, nb + TILE_B, tid);
            }
            __syncthreads();
        }

#pragma unroll
        for (int mt = 0; mt < 2; mt++)
#pragma unroll
            for (int h2 = 0; h2 < 2; h2++) {
                int mloc = wm + mt * 16 + (lane >> 2) + h2 * 8;
                int m = m0 + mloc;
                float rs = g_rowsum[b * Ll + m];
                float inv = (rs != 0.f) ? 1.f / rs : 0.f;
                const float* abar = g_abar + b * Hh + n0 + wn + (lane & 3) * 2;
                float* row = out + ((size_t)b * Ll + m) * 1024 + 512 + n0 + wn + (lane & 3) * 2;
#pragma unroll
                for (int nt = 0; nt < 4; nt++) {
                    float2 v;
                    float f0 = abar[nt * 8], f1 = abar[nt * 8 + 1];
                    v.x = (rs != 0.f) ? acc[mt][nt][h2 * 2]     * inv : f0;
                    v.y = (rs != 0.f) ? acc[mt][nt][h2 * 2 + 1] * inv : f1;
                    *reinterpret_cast<float2*>(row + nt * 8) = v;
                }
            }

        float4* out4 = reinterpret_cast<float4*>(out);
#pragma unroll
        for (int i = 0; i < 8; i++) {
            int idx = (i << 9) + tid;
            int row = idx >> 5, c = idx & 31;
            size_t orow = (size_t)b * Ll + m0 + row;
            out4[orow * 256 + (n0 >> 2) + c] = q4[orow * 128 + (n0 >> 2) + c];
        }
    } else {
        // ---- A side: A = P^T, B = q (transposed) ----
        const __half* Pb = g_P + (size_t)b * Ll * Ll + m0;   // P[k=q][m0+n]
        const __half* qb = g_qe + (size_t)b * Ll * Hh + n0;

        uint32_t va[4][2], vb[4][2];
        ldg_ht(va, Pb, Ll, tid);
        ldg_ht(vb, qb, Hh, tid);
        st_ht(va, sm, tid);
        st_ht(vb, sm + TILE_B, tid);
        __syncthreads();

        for (int kc = 0; kc < 16; kc++) {
            int nk = kc + 1;
            if (nk < 16) {
                ldg_ht(va, Pb + (size_t)(nk << 6) * Ll, Ll, tid);
                ldg_ht(vb, qb + (size_t)(nk << 6) * Hh, Hh, tid);
            }
            char* cur = sm + (kc & 1) * BUF2_B;
            mma_chunk1(acc, s2u(cur), s2u(cur + TILE_B), wm, wn, lane);
            if (nk < 16) {
                char* nb = sm + (nk & 1) * BUF2_B;
                st_ht(va, nb, tid);
                st_ht(vb, nb + TILE_B, tid);
            }
            __syncthreads();
        }

        const size_t OUT2 = (size_t)Bb * Ll * 1024;
#pragma unroll
        for (int mt = 0; mt < 2; mt++)
#pragma unroll
            for (int h2 = 0; h2 < 2; h2++) {
                int mloc = wm + mt * 16 + (lane >> 2) + h2 * 8;
                int m = m0 + mloc;
                float cs = g_colsum[b * Ll + m];
                float inv = (cs != 0.f) ? 1.f / cs : 0.f;
                const float* qbar = g_qbar + b * Hh + n0 + wn + (lane & 3) * 2;
                float* row = out + OUT2 + ((size_t)b * Ll + m) * 1024 + 512 + n0 + wn + (lane & 3) * 2;
#pragma unroll
                for (int nt = 0; nt < 4; nt++) {
                    float2 v;
                    float f0 = qbar[nt * 8], f1 = qbar[nt * 8 + 1];
                    v.x = (cs != 0.f) ? acc[mt][nt][h2 * 2]     * inv : f0;
                    v.y = (cs != 0.f) ? acc[mt][nt][h2 * 2 + 1] * inv : f1;
                    *reinterpret_cast<float2*>(row + nt * 8) = v;
                }
            }

        float4* out4 = reinterpret_cast<float4*>(out + OUT2);
#pragma unroll
        for (int i = 0; i < 8; i++) {
            int idx = (i << 9) + tid;
            int row = idx >> 5, c = idx & 31;
            size_t orow = (size_t)b * Ll + m0 + row;
            out4[orow * 256 + (n0 >> 2) + c] = a4[orow * 128 + (n0 >> 2) + c];
        }
    }
}

// ===========================================================================
extern "C" void kernel_launch(void* const* d_in, const int* in_sizes, int n_in,
                              void* d_out, int out_size)
{
    const float* q    = (const float*)d_in[0];
    const float* a    = (const float*)d_in[1];
    const int*   qm   = (const int*)  d_in[2];
    const int*   am   = (const int*)  d_in[3];
    const float* temp = (const float*)d_in[4];
    float* out = (float*)d_out;

    const int DS2 = 2 * BUF2_B;   // 73728
    cudaFuncSetAttribute(score_h,    cudaFuncAttributeMaxDynamicSharedMemorySize, DS2);
    cudaFuncSetAttribute(gemm_fused, cudaFuncAttributeMaxDynamicSharedMemorySize, DS2);

    prep_kernel<<<32768, 256>>>((const float4*)q, (const float4*)a);
    means_kernel<<<dim3(2, 32, 2), dim3(256, 4)>>>(q, a);
    score_h<<<dim3(8, 8, 32), 512, DS2>>>(qm, am, temp);
    gemm_fused<<<dim3(4, 8, 64), 512, DS2>>>((const float4*)q, (const float4*)a, out);
}

// round 15
// speedup vs baseline: 2.2865x; 1.1732x over previous
#include <cuda_runtime.h>
#include <cuda_fp16.h>
#include <cstdint>

#define Bb 32
#define Ll 1024
#define Hh 512

// Scratch
__device__ __half g_P[(size_t)Bb * Ll * Ll];      // exp(t*S) masked, fp16, 64 MB
__device__ float  g_rowsum[Bb * Ll];
__device__ float  g_colsum[Bb * Ll];
__device__ float  g_qbar[Bb * Hh];
__device__ float  g_abar[Bb * Hh];
__device__ __half g_qe[16777216], g_ae[16777216]; // fp16 operand caches

// ---------------------------------------------------------------------------
__device__ __forceinline__ uint32_t s2u(const void* p) {
    uint32_t a;
    asm("{ .reg .u64 t; cvta.to.shared.u64 t, %1; cvt.u32.u64 %0, t; }" : "=r"(a) : "l"(p));
    return a;
}
#define LDSM_X4(r0, r1, r2, r3, addr)                                        \
    asm volatile("ldmatrix.sync.aligned.m8n8.x4.shared.b16 {%0,%1,%2,%3}, [%4];" \
                 : "=r"(r0), "=r"(r1), "=r"(r2), "=r"(r3) : "r"(addr))
#define MMA_FP16(c, a, b)                                                    \
    asm volatile("mma.sync.aligned.m16n8k16.row.col.f32.f16.f16.f32 "        \
                 "{%0,%1,%2,%3}, {%4,%5,%6,%7}, {%8,%9}, {%0,%1,%2,%3};"     \
                 : "+f"((c)[0]), "+f"((c)[1]), "+f"((c)[2]), "+f"((c)[3])    \
                 : "r"((a)[0]), "r"((a)[1]), "r"((a)[2]), "r"((a)[3]),       \
                   "r"((b)[0]), "r"((b)[1]))

__device__ __forceinline__ uint32_t pack_h2(float x0, float x1) {
    __half2 h = __floats2half2_rn(x0, x1);
    return reinterpret_cast<uint32_t&>(h);
}

#define LDP 72
#define TILE_B 18432              // 128 rows x 72 halves x 2B
#define BUF2_B (2 * TILE_B)

// ===== fp16 tile loaders (256 threads) =====================================
// k-major tile [128 rows][64 k], vectorized uint4 (8 halves)
__device__ __forceinline__ void ldg_h(uint4 v[4],
    const __half* __restrict__ src, int ld, int k0, int tid)
{
#pragma unroll
    for (int i = 0; i < 4; i++) {
        int idx = (i << 8) + tid;
        int row = idx >> 3, c8 = idx & 7;
        v[i] = *reinterpret_cast<const uint4*>(src + (size_t)row * ld + k0 + (c8 << 3));
    }
}
__device__ __forceinline__ void st_h(const uint4 v[4], char* d, int tid)
{
#pragma unroll
    for (int i = 0; i < 4; i++) {
        int idx = (i << 8) + tid;
        int row = idx >> 3, c8 = idx & 7;
        uint32_t off = (uint32_t)(row * LDP + (c8 << 3)) * 2;
        *reinterpret_cast<uint4*>(d + off) = v[i];
    }
}
// transposed tile [n=128][k=64] from src[k*ld + n]
__device__ __forceinline__ void ldg_ht(uint32_t v[8][2],
    const __half* __restrict__ src, int ld, int tid)
{
#pragma unroll
    for (int i = 0; i < 8; i++) {
        int idx = (i << 8) + tid;
        int n = idx & 127, k4 = idx >> 7;
        const ushort* h0 = (const ushort*)src + (size_t)(k4 << 2) * ld + n;
        v[i][0] = (uint32_t)h0[0] | ((uint32_t)h0[ld] << 16);
        v[i][1] = (uint32_t)h0[2 * (size_t)ld] | ((uint32_t)h0[3 * (size_t)ld] << 16);
    }
}
__device__ __forceinline__ void st_ht(const uint32_t v[8][2], char* d, int tid)
{
#pragma unroll
    for (int i = 0; i < 8; i++) {
        int idx = (i << 8) + tid;
        int n = idx & 127, k4 = idx >> 7;
        uint32_t off = (uint32_t)(n * LDP + (k4 << 2)) * 2;
        *reinterpret_cast<uint2*>(d + off) = make_uint2(v[i][0], v[i][1]);
    }
}

// ---- fp16 chunk: warp tile 64(M) x 32(N), K=64 ----------------------------
// 6 ldmatrix.x4 per k-step for 16 MMAs (was 4 for 8)
__device__ __forceinline__ void mma_chunk64(float acc[4][4][4],
    uint32_t a_b, uint32_t b_b, int wm, int wn, int lane)
{
    const int l16 = lane & 15, lk = lane >> 4;
    const int bn = ((lane >> 4) << 3) + (lane & 7);
    const int bk = ((lane >> 3) & 1) << 3;
#pragma unroll
    for (int ks = 0; ks < 4; ks++) {
        const int k0 = ks << 4;
        uint32_t bf[4][2], af[4][4];
#pragma unroll
        for (int g = 0; g < 2; g++) {
            uint32_t boff = (uint32_t)((wn + g * 16 + bn) * LDP + k0 + bk) * 2;
            LDSM_X4(bf[2*g][0], bf[2*g][1], bf[2*g+1][0], bf[2*g+1][1], b_b + boff);
        }
#pragma unroll
        for (int mt = 0; mt < 4; mt++) {
            uint32_t aoff = (uint32_t)((wm + mt * 16 + l16) * LDP + k0 + lk * 8) * 2;
            LDSM_X4(af[mt][0], af[mt][1], af[mt][2], af[mt][3], a_b + aoff);
        }
#pragma unroll
        for (int mt = 0; mt < 4; mt++)
#pragma unroll
            for (int nt = 0; nt < 4; nt++)
                MMA_FP16(acc[mt][nt], af[mt], bf[nt]);
    }
}

// ===========================================================================
// Kernel 0: prep — q,a -> fp16 caches; zeroes the atomic sum arrays
// ===========================================================================
__global__ void __launch_bounds__(256) prep_kernel(
    const float4* __restrict__ q4, const float4* __restrict__ a4)
{
    int idx = blockIdx.x * 256 + threadIdx.x;
    if (idx < Bb * Ll) { g_rowsum[idx] = 0.f; g_colsum[idx] = 0.f; }
    int isA = idx >> 22;
    int base = idx & 4194303;
    float4 v = (isA ? a4 : q4)[base];
    uint2* de = reinterpret_cast<uint2*>(isA ? g_ae : g_qe);
    de[base] = make_uint2(pack_h2(v.x, v.y), pack_h2(v.z, v.w));
}

// ===========================================================================
// Kernel 0b: per-batch column means (uniform-softmax fallback)
// ===========================================================================
__global__ void means_kernel(const float* __restrict__ q, const float* __restrict__ a)
{
    const float* src = blockIdx.z ? a : q;
    float* dst = blockIdx.z ? g_abar : g_qbar;
    const int b = blockIdx.y;
    const int h = blockIdx.x * 256 + threadIdx.x;
    float s = 0.f;
    const int r0 = threadIdx.y * 256;
    const float* p = src + ((size_t)b * Ll + r0) * Hh + h;
    for (int r = 0; r < 256; r++) s += p[(size_t)r * Hh];
    __shared__ float red[4][256];
    red[threadIdx.y][threadIdx.x] = s;
    __syncthreads();
    if (threadIdx.y == 0) {
        float t = red[0][threadIdx.x] + red[1][threadIdx.x]
                + red[2][threadIdx.x] + red[3][threadIdx.x];
        dst[b * Hh + h] = t * (1.0f / 1024.0f);
    }
}

// ===========================================================================
// Kernel 1: P = exp(temp * q a^T) masked + fused row/col partial sums
// 256 threads, warp grid 2(M)x4(N), warp tile 64x32
// ===========================================================================
__global__ void __launch_bounds__(256, 2) score_h(
    const int* __restrict__ qm, const int* __restrict__ am,
    const float* __restrict__ temp)
{
    extern __shared__ char sm[];
    __shared__ int s_qm[128], s_am[128];
    __shared__ float srow[128], scol[128];

    const int tid = threadIdx.x, lane = tid & 31, wid = tid >> 5;
    const int wm = (wid & 1) * 64, wn = (wid >> 1) * 32;
    const int b = blockIdx.z, m0 = blockIdx.y << 7, n0 = blockIdx.x << 7;

    if (tid < 128) {
        s_qm[tid] = qm[b * Ll + m0 + tid];
        s_am[tid] = am[b * Ll + n0 + tid];
        srow[tid] = 0.f;
        scol[tid] = 0.f;
    }

    const __half* qb = g_qe + ((size_t)b * Ll + m0) * Hh;
    const __half* ab = g_ae + ((size_t)b * Ll + n0) * Hh;

    uint4 va[4], vb[4];
    ldg_h(va, qb, Hh, 0, tid);
    ldg_h(vb, ab, Hh, 0, tid);
    st_h(va, sm, tid);
    st_h(vb, sm + TILE_B, tid);
    __syncthreads();

    float acc[4][4][4] = {};
    for (int kc = 0; kc < 8; kc++) {
        int nk = kc + 1;
        if (nk < 8) {
            ldg_h(va, qb, Hh, nk << 6, tid);
            ldg_h(vb, ab, Hh, nk << 6, tid);
        }
        char* cur = sm + (kc & 1) * BUF2_B;
        mma_chunk64(acc, s2u(cur), s2u(cur + TILE_B), wm, wn, lane);
        if (nk < 8) {
            char* nb = sm + (nk & 1) * BUF2_B;
            st_h(va, nb, tid);
            st_h(vb, nb + TILE_B, tid);
        }
        __syncthreads();
    }

    const float t = *temp;
    float cp[4][2] = {};
#pragma unroll
    for (int mt = 0; mt < 4; mt++)
#pragma unroll
        for (int h2 = 0; h2 < 2; h2++) {
            int mloc = wm + mt * 16 + (lane >> 2) + h2 * 8;
            int qv = s_qm[mloc];
            ushort* row = (ushort*)g_P + ((size_t)b * Ll + m0 + mloc) * Ll
                        + n0 + wn + (lane & 3) * 2;
            float rp = 0.f;
#pragma unroll
            for (int nt = 0; nt < 4; nt++) {
                int c = wn + nt * 8 + (lane & 3) * 2;
                float e0 = (qv && s_am[c])     ? __expf(acc[mt][nt][h2 * 2]     * t) : 0.f;
                float e1 = (qv && s_am[c + 1]) ? __expf(acc[mt][nt][h2 * 2 + 1] * t) : 0.f;
                uint32_t pk = pack_h2(e0, e1);
                *reinterpret_cast<uint32_t*>(row + nt * 8) = pk;
                float2 f = __half22float2(*reinterpret_cast<__half2*>(&pk));
                rp += f.x + f.y;
                cp[nt][0] += f.x;
                cp[nt][1] += f.y;
            }
            atomicAdd(&srow[mloc], rp);
        }
#pragma unroll
    for (int nt = 0; nt < 4; nt++) {
        int c = wn + nt * 8 + (lane & 3) * 2;
        atomicAdd(&scol[c], cp[nt][0]);
        atomicAdd(&scol[c + 1], cp[nt][1]);
    }
    __syncthreads();
    if (tid < 128) {
        atomicAdd(&g_rowsum[b * Ll + m0 + tid], srow[tid]);
        atomicAdd(&g_colsum[b * Ll + n0 + tid], scol[tid]);
    }
}

// ===========================================================================
// Kernel 2: fused output GEMMs. z<32: Q side; z>=32: A side.
// 256 threads, warp tile 64x32
// ===========================================================================
__global__ void __launch_bounds__(256, 2) gemm_fused(
    const float4* __restrict__ q4, const float4* __restrict__ a4,
    float* __restrict__ out)
{
    extern __shared__ char sm[];
    const int tid = threadIdx.x, lane = tid & 31, wid = tid >> 5;
    const int wm = (wid & 1) * 64, wn = (wid >> 1) * 32;
    const int z = blockIdx.z;
    const int isA = z >> 5;
    const int b = z & 31;
    const int m0 = blockIdx.y << 7, n0 = blockIdx.x << 7;

    float acc[4][4][4] = {};

    if (!isA) {
        const __half* Pb = g_P + ((size_t)b * Ll + m0) * Ll;
        const __half* ab = g_ae + (size_t)b * Ll * Hh + n0;

        uint4 va[4];
        uint32_t vb[8][2];
        ldg_h(va, Pb, Ll, 0, tid);
        ldg_ht(vb, ab, Hh, tid);
        st_h(va, sm, tid);
        st_ht(vb, sm + TILE_B, tid);
        __syncthreads();

        for (int kc = 0; kc < 16; kc++) {
            int nk = kc + 1;
            if (nk < 16) {
                ldg_h(va, Pb, Ll, nk << 6, tid);
                ldg_ht(vb, ab + (size_t)(nk << 6) * Hh, Hh, tid);
            }
            char* cur = sm + (kc & 1) * BUF2_B;
            mma_chunk64(acc, s2u(cur), s2u(cur + TILE_B), wm, wn, lane);
            if (nk < 16) {
                char* nb = sm + (nk & 1) * BUF2_B;
                st_h(va, nb, tid);
                st_ht(vb, nb + TILE_B, tid);
            }
            __syncthreads();
        }

#pragma unroll
        for (int mt = 0; mt < 4; mt++)
#pragma unroll
            for (int h2 = 0; h2 < 2; h2++) {
                int mloc = wm + mt * 16 + (lane >> 2) + h2 * 8;
                int m = m0 + mloc;
                float rs = g_rowsum[b * Ll + m];
                float inv = (rs != 0.f) ? 1.f / rs : 0.f;
                const float* abar = g_abar + b * Hh + n0 + wn + (lane & 3) * 2;
                float* row = out + ((size_t)b * Ll + m) * 1024 + 512 + n0 + wn + (lane & 3) * 2;
#pragma unroll
                for (int nt = 0; nt < 4; nt++) {
                    float2 v;
                    float f0 = abar[nt * 8], f1 = abar[nt * 8 + 1];
                    v.x = (rs != 0.f) ? acc[mt][nt][h2 * 2]     * inv : f0;
                    v.y = (rs != 0.f) ? acc[mt][nt][h2 * 2 + 1] * inv : f1;
                    *reinterpret_cast<float2*>(row + nt * 8) = v;
                }
            }

        float4* out4 = reinterpret_cast<float4*>(out);
#pragma unroll
        for (int i = 0; i < 16; i++) {
            int idx = (i << 8) + tid;
            int row = idx >> 5, c = idx & 31;
            size_t orow = (size_t)b * Ll + m0 + row;
            out4[orow * 256 + (n0 >> 2) + c] = q4[orow * 128 + (n0 >> 2) + c];
        }
    } else {
        const __half* Pb = g_P + (size_t)b * Ll * Ll + m0;   // P[k=q][m0+n]
        const __half* qb = g_qe + (size_t)b * Ll * Hh + n0;

        uint32_t va[8][2], vb[8][2];
        ldg_ht(va, Pb, Ll, tid);
        ldg_ht(vb, qb, Hh, tid);
        st_ht(va, sm, tid);
        st_ht(vb, sm + TILE_B, tid);
        __syncthreads();

        for (int kc = 0; kc < 16; kc++) {
            int nk = kc + 1;
            if (nk < 16) {
                ldg_ht(va, Pb + (size_t)(nk << 6) * Ll, Ll, tid);
                ldg_ht(vb, qb + (size_t)(nk << 6) * Hh, Hh, tid);
            }
            char* cur = sm + (kc & 1) * BUF2_B;
            mma_chunk64(acc, s2u(cur), s2u(cur + TILE_B), wm, wn, lane);
            if (nk < 16) {
                char* nb = sm + (nk & 1) * BUF2_B;
                st_ht(va, nb, tid);
                st_ht(vb, nb + TILE_B, tid);
            }
            __syncthreads();
        }

        const size_t OUT2 = (size_t)Bb * Ll * 1024;
#pragma unroll
        for (int mt = 0; mt < 4; mt++)
#pragma unroll
            for (int h2 = 0; h2 < 2; h2++) {
                int mloc = wm + mt * 16 + (lane >> 2) + h2 * 8;
                int m = m0 + mloc;
                float cs = g_colsum[b * Ll + m];
                float inv = (cs != 0.f) ? 1.f / cs : 0.f;
                const float* qbar = g_qbar + b * Hh + n0 + wn + (lane & 3) * 2;
                float* row = out + OUT2 + ((size_t)b * Ll + m) * 1024 + 512 + n0 + wn + (lane & 3) * 2;
#pragma unroll
                for (int nt = 0; nt < 4; nt++) {
                    float2 v;
                    float f0 = qbar[nt * 8], f1 = qbar[nt * 8 + 1];
                    v.x = (cs != 0.f) ? acc[mt][nt][h2 * 2]     * inv : f0;
                    v.y = (cs != 0.f) ? acc[mt][nt][h2 * 2 + 1] * inv : f1;
                    *reinterpret_cast<float2*>(row + nt * 8) = v;
                }
            }

        float4* out4 = reinterpret_cast<float4*>(out + OUT2);
#pragma unroll
        for (int i = 0; i < 16; i++) {
            int idx = (i << 8) + tid;
            int row = idx >> 5, c = idx & 31;
            size_t orow = (size_t)b * Ll + m0 + row;
            out4[orow * 256 + (n0 >> 2) + c] = a4[orow * 128 + (n0 >> 2) + c];
        }
    }
}

// ===========================================================================
extern "C" void kernel_launch(void* const* d_in, const int* in_sizes, int n_in,
                              void* d_out, int out_size)
{
    const float* q    = (const float*)d_in[0];
    const float* a    = (const float*)d_in[1];
    const int*   qm   = (const int*)  d_in[2];
    const int*   am   = (const int*)  d_in[3];
    const float* temp = (const float*)d_in[4];
    float* out = (float*)d_out;

    const int DS2 = 2 * BUF2_B;   // 73728
    cudaFuncSetAttribute(score_h,    cudaFuncAttributeMaxDynamicSharedMemorySize, DS2);
    cudaFuncSetAttribute(gemm_fused, cudaFuncAttributeMaxDynamicSharedMemorySize, DS2);

    prep_kernel<<<32768, 256>>>((const float4*)q, (const float4*)a);
    means_kernel<<<dim3(2, 32, 2), dim3(256, 4)>>>(q, a);
    score_h<<<dim3(8, 8, 32), 256, DS2>>>(qm, am, temp);
    gemm_fused<<<dim3(4, 8, 64), 256, DS2>>>((const float4*)q, (const float4*)a, out);
}

// round 16
// speedup vs baseline: 2.7151x; 1.1874x over previous
#include <cuda_runtime.h>
#include <cuda_fp16.h>
#include <cstdint>

#define Bb 32
#define Ll 1024
#define Hh 512

// Scratch
__device__ __half g_P [(size_t)Bb * Ll * Ll];     // exp(t*S) masked, [b][q][a]
__device__ __half g_PT[(size_t)Bb * Ll * Ll];     // transpose,      [b][a][q]
__device__ float  g_rowsum[Bb * Ll];
__device__ float  g_colsum[Bb * Ll];
__device__ float  g_qbar[Bb * Hh];
__device__ float  g_abar[Bb * Hh];
__device__ __half g_qe[16777216], g_ae[16777216]; // [b][l][h] fp16
__device__ __half g_qt[16777216], g_at[16777216]; // [b][h][l] fp16

// ---------------------------------------------------------------------------
__device__ __forceinline__ uint32_t s2u(const void* p) {
    uint32_t a;
    asm("{ .reg .u64 t; cvta.to.shared.u64 t, %1; cvt.u32.u64 %0, t; }" : "=r"(a) : "l"(p));
    return a;
}
#define LDSM_X4(r0, r1, r2, r3, addr)                                        \
    asm volatile("ldmatrix.sync.aligned.m8n8.x4.shared.b16 {%0,%1,%2,%3}, [%4];" \
                 : "=r"(r0), "=r"(r1), "=r"(r2), "=r"(r3) : "r"(addr))
#define MMA_FP16(c, a, b)                                                    \
    asm volatile("mma.sync.aligned.m16n8k16.row.col.f32.f16.f16.f32 "        \
                 "{%0,%1,%2,%3}, {%4,%5,%6,%7}, {%8,%9}, {%0,%1,%2,%3};"     \
                 : "+f"((c)[0]), "+f"((c)[1]), "+f"((c)[2]), "+f"((c)[3])    \
                 : "r"((a)[0]), "r"((a)[1]), "r"((a)[2]), "r"((a)[3]),       \
                   "r"((b)[0]), "r"((b)[1]))
#define CP_ASYNC16(dst, src)                                                 \
    asm volatile("cp.async.cg.shared.global [%0], [%1], 16;" :: "r"(dst), "l"(src))
#define CP_COMMIT() asm volatile("cp.async.commit_group;")
#define CP_WAIT1()  asm volatile("cp.async.wait_group 1;")

__device__ __forceinline__ uint32_t pack_h2(float x0, float x1) {
    __half2 h = __floats2half2_rn(x0, x1);
    return reinterpret_cast<uint32_t&>(h);
}

// Swizzled tile: 128 rows x 64 halves (128 B/row); element (row, k8) at
// byte offset row*128 + ((k8 ^ (row & 7)) << 4). 16B aligned, ldmatrix
// conflict-free across 8 consecutive rows.
#define SWOFF(row, k8) (((uint32_t)(row) << 7) + (((uint32_t)((k8) ^ ((row) & 7))) << 4))
#define TILE_B 16384
#define BUF_B  (2 * TILE_B)    // A + B tile per stage
#define NSTAGE 3

// ---- cp.async loader: k-major tile [128 rows][64 k] from src[row*ld+k0+k] --
__device__ __forceinline__ void cpa_tile(uint32_t sbase,
    const __half* __restrict__ src, int ld, int k0, int tid)
{
#pragma unroll
    for (int i = 0; i < 4; i++) {
        int idx = (i << 8) + tid;
        int row = idx >> 3, k8 = idx & 7;
        uint32_t dst = sbase + SWOFF(row, k8);
        CP_ASYNC16(dst, src + (size_t)row * ld + k0 + (k8 << 3));
    }
}

// ---- fp16 chunk: warp tile 64(M) x 32(N), K=64, swizzled smem -------------
__device__ __forceinline__ void mma_chunk64(float acc[4][4][4],
    uint32_t a_b, uint32_t b_b, int wm, int wn, int lane)
{
    const int l16 = lane & 15, lk = lane >> 4;
    const int bn = ((lane >> 4) << 3) + (lane & 7);
    const int bkb = (lane >> 3) & 1;
#pragma unroll
    for (int ks = 0; ks < 4; ks++) {
        uint32_t bf[4][2], af[4][4];
#pragma unroll
        for (int g = 0; g < 2; g++) {
            uint32_t boff = b_b + SWOFF(wn + g * 16 + bn, ks * 2 + bkb);
            LDSM_X4(bf[2*g][0], bf[2*g][1], bf[2*g+1][0], bf[2*g+1][1], boff);
        }
#pragma unroll
        for (int mt = 0; mt < 4; mt++) {
            uint32_t aoff = a_b + SWOFF(wm + mt * 16 + l16, ks * 2 + lk);
            LDSM_X4(af[mt][0], af[mt][1], af[mt][2], af[mt][3], aoff);
        }
#pragma unroll
        for (int mt = 0; mt < 4; mt++)
#pragma unroll
            for (int nt = 0; nt < 4; nt++)
                MMA_FP16(acc[mt][nt], af[mt], bf[nt]);
    }
}

// ===========================================================================
// Kernel 0: prep — q,a -> fp16 caches [b][l][h]; zero sum arrays
// ===========================================================================
__global__ void __launch_bounds__(256) prep_kernel(
    const float4* __restrict__ q4, const float4* __restrict__ a4)
{
    int idx = blockIdx.x * 256 + threadIdx.x;
    if (idx < Bb * Ll) { g_rowsum[idx] = 0.f; g_colsum[idx] = 0.f; }
    int isA = idx >> 22;
    int base = idx & 4194303;
    float4 v = (isA ? a4 : q4)[base];
    uint2* de = reinterpret_cast<uint2*>(isA ? g_ae : g_qe);
    de[base] = make_uint2(pack_h2(v.x, v.y), pack_h2(v.z, v.w));
}

// ===========================================================================
// Kernel 0a: transpose q,a -> [b][h][l] fp16 (64x64 tiles via smem)
// grid (Ll/64, Hh/64, 64)  z = isA*32 + b
// ===========================================================================
__global__ void __launch_bounds__(256) transpose_kernel(
    const float* __restrict__ q, const float* __restrict__ a)
{
    __shared__ float sm[64][65];
    const int isA = blockIdx.z >> 5;
    const int b = blockIdx.z & 31;
    const int l0 = blockIdx.x * 64, h0 = blockIdx.y * 64;
    const float* src = (isA ? a : q) + (size_t)b * Ll * Hh;
    __half* dst = (isA ? g_at : g_qt) + (size_t)b * Hh * Ll;

    const int tid = threadIdx.x;
    const int r = tid >> 4, c4 = (tid & 15) << 2;
#pragma unroll
    for (int i = 0; i < 4; i++) {
        int l = r + i * 16;
        float4 v = *reinterpret_cast<const float4*>(src + (size_t)(l0 + l) * Hh + h0 + c4);
        sm[l][c4] = v.x; sm[l][c4 + 1] = v.y; sm[l][c4 + 2] = v.z; sm[l][c4 + 3] = v.w;
    }
    __syncthreads();
#pragma unroll
    for (int i = 0; i < 4; i++) {
        int h = r + i * 16;
        uint2 o = make_uint2(pack_h2(sm[c4][h], sm[c4 + 1][h]),
                             pack_h2(sm[c4 + 2][h], sm[c4 + 3][h]));
        *reinterpret_cast<uint2*>(dst + (size_t)(h0 + h) * Ll + l0 + c4) = o;
    }
}

// ===========================================================================
// Kernel 0b: per-batch column means (uniform-softmax fallback)
// ===========================================================================
__global__ void means_kernel(const float* __restrict__ q, const float* __restrict__ a)
{
    const float* src = blockIdx.z ? a : q;
    float* dst = blockIdx.z ? g_abar : g_qbar;
    const int b = blockIdx.y;
    const int h = blockIdx.x * 256 + threadIdx.x;
    float s = 0.f;
    const int r0 = threadIdx.y * 256;
    const float* p = src + ((size_t)b * Ll + r0) * Hh + h;
    for (int r = 0; r < 256; r++) s += p[(size_t)r * Hh];
    __shared__ float red[4][256];
    red[threadIdx.y][threadIdx.x] = s;
    __syncthreads();
    if (threadIdx.y == 0) {
        float t = red[0][threadIdx.x] + red[1][threadIdx.x]
                + red[2][threadIdx.x] + red[3][threadIdx.x];
        dst[b * Hh + h] = t * (1.0f / 1024.0f);
    }
}

// ===========================================================================
// Kernel 1: P/PT = exp(temp * q a^T) masked + fused row/col sums
// cp.async 3-stage; PT written via smem-staged transpose
// ===========================================================================
#define TP 144   // PT staging pitch (halves); 288B rows, 16B-divisible
__global__ void __launch_bounds__(256, 2) score_h(
    const int* __restrict__ qm, const int* __restrict__ am,
    const float* __restrict__ temp)
{
    extern __shared__ char sm[];
    __shared__ int s_qm[128], s_am[128];
    __shared__ float srow[128], scol[128];

    const int tid = threadIdx.x, lane = tid & 31, wid = tid >> 5;
    const int wm = (wid & 1) * 64, wn = (wid >> 1) * 32;
    const int b = blockIdx.z, m0 = blockIdx.y << 7, n0 = blockIdx.x << 7;

    if (tid < 128) {
        s_qm[tid] = qm[b * Ll + m0 + tid];
        s_am[tid] = am[b * Ll + n0 + tid];
        srow[tid] = 0.f;
        scol[tid] = 0.f;
    }

    const __half* qb = g_qe + ((size_t)b * Ll + m0) * Hh;
    const __half* ab = g_ae + ((size_t)b * Ll + n0) * Hh;
    const uint32_t smb = s2u(sm);

    cpa_tile(smb,          qb, Hh, 0, tid);
    cpa_tile(smb + TILE_B, ab, Hh, 0, tid);
    CP_COMMIT();
    cpa_tile(smb + BUF_B,          qb, Hh, 64, tid);
    cpa_tile(smb + BUF_B + TILE_B, ab, Hh, 64, tid);
    CP_COMMIT();

    float acc[4][4][4] = {};
    for (int kc = 0; kc < 8; kc++) {
        CP_WAIT1();
        __syncthreads();
        int nk = kc + 2;
        if (nk < 8) {
            uint32_t nb = smb + (nk % NSTAGE) * BUF_B;
            cpa_tile(nb,          qb, Hh, nk << 6, tid);
            cpa_tile(nb + TILE_B, ab, Hh, nk << 6, tid);
        }
        CP_COMMIT();
        uint32_t cur = smb + (kc % NSTAGE) * BUF_B;
        mma_chunk64(acc, cur, cur + TILE_B, wm, wn, lane);
    }
    __syncthreads();   // stage buffers free for PT staging

    const float t = *temp;
    float cp[4][2] = {};
#pragma unroll
    for (int mt = 0; mt < 4; mt++)
#pragma unroll
        for (int h2 = 0; h2 < 2; h2++) {
            int mloc = wm + mt * 16 + (lane >> 2) + h2 * 8;
            int qv = s_qm[mloc];
            ushort* row = (ushort*)g_P + ((size_t)b * Ll + m0 + mloc) * Ll
                        + n0 + wn + (lane & 3) * 2;
            float rp = 0.f;
#pragma unroll
            for (int nt = 0; nt < 4; nt++) {
                int c = wn + nt * 8 + (lane & 3) * 2;
                float e0 = (qv && s_am[c])     ? __expf(acc[mt][nt][h2 * 2]     * t) : 0.f;
                float e1 = (qv && s_am[c + 1]) ? __expf(acc[mt][nt][h2 * 2 + 1] * t) : 0.f;
                uint32_t pk = pack_h2(e0, e1);
                *reinterpret_cast<uint32_t*>(row + nt * 8) = pk;
                // PT staging (transposed) into smem
                *reinterpret_cast<ushort*>(sm + ((c)     * TP + mloc) * 2) = (ushort)(pk & 0xffff);
                *reinterpret_cast<ushort*>(sm + ((c + 1) * TP + mloc) * 2) = (ushort)(pk >> 16);
                float2 f = __half22float2(*reinterpret_cast<__half2*>(&pk));
                rp += f.x + f.y;
                cp[nt][0] += f.x;
                cp[nt][1] += f.y;
            }
            atomicAdd(&srow[mloc], rp);
        }
#pragma unroll
    for (int nt = 0; nt < 4; nt++) {
        int c = wn + nt * 8 + (lane & 3) * 2;
        atomicAdd(&scol[c], cp[nt][0]);
        atomicAdd(&scol[c + 1], cp[nt][1]);
    }
    __syncthreads();
    if (tid < 128) {
        atomicAdd(&g_rowsum[b * Ll + m0 + tid], srow[tid]);
        atomicAdd(&g_colsum[b * Ll + n0 + tid], scol[tid]);
    }
    // coalesced PT writes: each thread 64 halves of one a-row
    {
        int r = tid >> 1;                 // a-row within tile
        int q0 = (tid & 1) << 6;          // q offset 0/64
        ushort* drow = (ushort*)g_PT + ((size_t)b * Ll + n0 + r) * Ll + m0 + q0;
#pragma unroll
        for (int j = 0; j < 8; j++) {
            uint4 v = *reinterpret_cast<uint4*>(sm + ((size_t)r * TP + q0 + j * 8) * 2);
            *reinterpret_cast<uint4*>(drow + j * 8) = v;
        }
    }
}

// ===========================================================================
// Kernel 2: fused output GEMMs — unified sides, cp.async 3-stage.
// z<32: q_s = P @ at / rowsum (+copy q); z>=32: a_s = PT @ qt / colsum (+copy a)
// ===========================================================================
__global__ void __launch_bounds__(256, 2) gemm_fused(
    const float4* __restrict__ q4, const float4* __restrict__ a4,
    float* __restrict__ out)
{
    extern __shared__ char sm[];
    const int tid = threadIdx.x, lane = tid & 31, wid = tid >> 5;
    const int wm = (wid & 1) * 64, wn = (wid >> 1) * 32;
    const int z = blockIdx.z;
    const int isA = z >> 5;
    const int b = z & 31;
    const int m0 = blockIdx.y << 7, n0 = blockIdx.x << 7;

    const __half* Amat = (isA ? g_PT : g_P) + ((size_t)b * Ll + m0) * Ll;
    const __half* Bmat = (isA ? g_qt : g_at) + ((size_t)b * Hh + n0) * Ll;
    const float*  sums = (isA ? g_colsum : g_rowsum) + b * Ll;
    const float*  bar  = (isA ? g_qbar : g_abar) + b * Hh;
    const uint32_t smb = s2u(sm);

    cpa_tile(smb,          Amat, Ll, 0, tid);
    cpa_tile(smb + TILE_B, Bmat, Ll, 0, tid);
    CP_COMMIT();
    cpa_tile(smb + BUF_B,          Amat, Ll, 64, tid);
    cpa_tile(smb + BUF_B + TILE_B, Bmat, Ll, 64, tid);
    CP_COMMIT();

    float acc[4][4][4] = {};
    for (int kc = 0; kc < 16; kc++) {
        CP_WAIT1();
        __syncthreads();
        int nk = kc + 2;
        if (nk < 16) {
            uint32_t nb = smb + (nk % NSTAGE) * BUF_B;
            cpa_tile(nb,          Amat, Ll, nk << 6, tid);
            cpa_tile(nb + TILE_B, Bmat, Ll, nk << 6, tid);
        }
        CP_COMMIT();
        uint32_t cur = smb + (kc % NSTAGE) * BUF_B;
        mma_chunk64(acc, cur, cur + TILE_B, wm, wn, lane);
    }

    const size_t obase = (isA ? (size_t)Bb * Ll * 1024 : 0);
#pragma unroll
    for (int mt = 0; mt < 4; mt++)
#pragma unroll
        for (int h2 = 0; h2 < 2; h2++) {
            int mloc = wm + mt * 16 + (lane >> 2) + h2 * 8;
            int m = m0 + mloc;
            float rs = sums[m];
            float inv = (rs != 0.f) ? 1.f / rs : 0.f;
            const float* bb = bar + n0 + wn + (lane & 3) * 2;
            float* row = out + obase + ((size_t)b * Ll + m) * 1024 + 512 + n0 + wn + (lane & 3) * 2;
#pragma unroll
            for (int nt = 0; nt < 4; nt++) {
                float2 v;
                float f0 = bb[nt * 8], f1 = bb[nt * 8 + 1];
                v.x = (rs != 0.f) ? acc[mt][nt][h2 * 2]     * inv : f0;
                v.y = (rs != 0.f) ? acc[mt][nt][h2 * 2 + 1] * inv : f1;
                *reinterpret_cast<float2*>(row + nt * 8) = v;
            }
        }

    // copy the raw input block into the lower half
    const float4* src4 = isA ? a4 : q4;
    float4* out4 = reinterpret_cast<float4*>(out + obase);
#pragma unroll
    for (int i = 0; i < 16; i++) {
        int idx = (i << 8) + tid;
        int row = idx >> 5, c = idx & 31;
        size_t orow = (size_t)b * Ll + m0 + row;
        out4[orow * 256 + (n0 >> 2) + c] = src4[orow * 128 + (n0 >> 2) + c];
    }
}

// ===========================================================================
extern "C" void kernel_launch(void* const* d_in, const int* in_sizes, int n_in,
                              void* d_out, int out_size)
{
    const float* q    = (const float*)d_in[0];
    const float* a    = (const float*)d_in[1];
    const int*   qm   = (const int*)  d_in[2];
    const int*   am   = (const int*)  d_in[3];
    const float* temp = (const float*)d_in[4];
    float* out = (float*)d_out;

    const int DS = NSTAGE * BUF_B;   // 98304
    cudaFuncSetAttribute(score_h,    cudaFuncAttributeMaxDynamicSharedMemorySize, DS);
    cudaFuncSetAttribute(gemm_fused, cudaFuncAttributeMaxDynamicSharedMemorySize, DS);

    prep_kernel<<<32768, 256>>>((const float4*)q, (const float4*)a);
    transpose_kernel<<<dim3(16, 8, 64), 256>>>(q, a);
    means_kernel<<<dim3(2, 32, 2), dim3(256, 4)>>>(q, a);
    score_h<<<dim3(8, 8, 32), 256, DS>>>(qm, am, temp);
    gemm_fused<<<dim3(4, 8, 64), 256, DS>>>((const float4*)q, (const float4*)a, out);
}